// round 8
// baseline (speedup 1.0000x reference)
#include <cuda_runtime.h>
#include <cuda_fp16.h>
#include <cstdint>
#include <math.h>

// ---------------- problem constants ----------------
#define DIMC  128
#define TT    16
#define INNER 256
#define SEQS  8192
#define ROWS  (SEQS*TT)         // 131072
#define UPCOLS 512

// ---------------- scratch (static device, no allocs) ----------------
__device__ __half g_XS[(size_t)ROWS*DIMC];   // [row][128] fp16
__device__ float  g_UP[(size_t)ROWS*UPCOLS]; // [row][512] fp32
__device__ __half g_HS[(size_t)ROWS*INNER];  // [row][256] fp16
__device__ float  g_OT[(size_t)ROWS*DIMC];   // [row][128] fp32
__device__ __half g_WTU[512*128];            // W_up^T  [n][k] fp16
__device__ __half g_WTD[128*256];            // W_down^T [n][k] fp16

// ---------------- helpers ----------------
__device__ __forceinline__ float siluf(float x){ return x / (1.f + __expf(-x)); }
__device__ __forceinline__ uint32_t smem_u32(const void* p){
    uint32_t a;
    asm("{ .reg .u64 t; cvta.to.shared.u64 t, %1; cvt.u32.u64 %0, t; }" : "=r"(a) : "l"(p));
    return a;
}

// ---------------- kernel: (b,c,t,h,w) -> XS[seq][t][c] (fp16) ----------------
__global__ void __launch_bounds__(256) k_transpose_in(const float* __restrict__ x,
                                                      __half* __restrict__ XS) {
    __shared__ float tile[128*33];
    int bid = blockIdx.x;
    int b = bid >> 9;
    int t = (bid >> 5) & 15;
    int h = bid & 31;
    const float* src = x + ((size_t)(b*128)*16 + t) * 1024 + h*32;
    for (int idx = threadIdx.x; idx < 128*32; idx += 256) {
        int c = idx >> 5, w = idx & 31;
        tile[c*33 + w] = src[(size_t)c*16384 + w];
    }
    __syncthreads();
    size_t base = ((size_t)(b*1024 + h*32) * 16 + t) * 128;
    for (int idx = threadIdx.x; idx < 2048; idx += 256) {
        int w = idx >> 6, c2 = idx & 63;
        __half2 v = __float22half2_rn(make_float2(tile[(2*c2)*33 + w],
                                                  tile[(2*c2+1)*33 + w]));
        *(__half2*)(XS + base + (size_t)w*2048 + 2*c2) = v;
    }
}

// ---------------- kernel: OT[row][c] -> out (b,c,t,h,w) ----------------
__global__ void __launch_bounds__(256) k_transpose_out(const float* __restrict__ OT,
                                                       float* __restrict__ out) {
    __shared__ float tile[128*33];
    int bid = blockIdx.x;
    int b = bid >> 9;
    int t = (bid >> 5) & 15;
    int h = bid & 31;
    size_t base = ((size_t)(b*1024 + h*32) * 16 + t) * 128;
    for (int idx = threadIdx.x; idx < 32*128; idx += 256) {
        int w = idx >> 7, c = idx & 127;
        tile[c*33 + w] = OT[base + (size_t)w*2048 + c];
    }
    __syncthreads();
    float* dst = out + ((size_t)(b*128)*16 + t) * 1024 + h*32;
    for (int idx = threadIdx.x; idx < 128*32; idx += 256) {
        int c = idx >> 5, w = idx & 31;
        dst[(size_t)c*16384 + w] = tile[c*33 + w];
    }
}

// ---------------- weight transpose to fp16: Wt[n][k] = W[k][n] ----------------
__global__ void k_wt(const float* __restrict__ W, __half* __restrict__ Wt, int K, int N){
    int idx = blockIdx.x*256 + threadIdx.x;
    if (idx < K*N) { int k = idx / N, n = idx - k*N; Wt[(size_t)n*K + k] = __float2half(W[idx]); }
}

// ---------------- fp16 warp-MMA GEMM: C[M,Ng] = A[M,K] @ Bt[Ng,K]^T ----------------
__global__ void __launch_bounds__(256) k_gemm_h(const __half* __restrict__ A,
        const __half* __restrict__ Bt, float* __restrict__ C, int Ng, int Kf) {
    __shared__ __align__(16) __half As[2][128*40];
    __shared__ __align__(16) __half Bs[2][128*40];
    const int tid  = threadIdx.x;
    const int lane = tid & 31, warp = tid >> 5;
    const int gid  = lane >> 2, tig = lane & 3;
    const int wm0  = (warp >> 1) * 32;
    const int wn0  = (warp & 1) * 64;
    const int m0 = blockIdx.y * 128, n0 = blockIdx.x * 128;
    const int nk = Kf >> 5;

    uint32_t sA0 = smem_u32(As[0]), sA1 = smem_u32(As[1]);
    uint32_t sB0 = smem_u32(Bs[0]), sB1 = smem_u32(Bs[1]);

    float acc[2][8][4];
#pragma unroll
    for (int i = 0; i < 2; i++)
#pragma unroll
        for (int j = 0; j < 8; j++)
#pragma unroll
            for (int e = 0; e < 4; e++) acc[i][j][e] = 0.f;

    auto issue = [&](int kb, int buf){
        uint32_t da_base = buf ? sA1 : sA0;
        uint32_t db_base = buf ? sB1 : sB0;
#pragma unroll
        for (int r = 0; r < 2; r++) {
            int idx = tid + 256*r;
            int row = idx >> 2, c16 = idx & 3;
            const __half* ga = A  + (size_t)(m0+row)*Kf + kb + c16*8;
            const __half* gb = Bt + (size_t)(n0+row)*Kf + kb + c16*8;
            uint32_t da = da_base + row*80 + c16*16;
            uint32_t db = db_base + row*80 + c16*16;
            asm volatile("cp.async.cg.shared.global [%0], [%1], 16;" :: "r"(da), "l"(ga));
            asm volatile("cp.async.cg.shared.global [%0], [%1], 16;" :: "r"(db), "l"(gb));
        }
        asm volatile("cp.async.commit_group;");
    };

    issue(0, 0);
    for (int kc = 0; kc < nk; kc++) {
        if (kc + 1 < nk) {
            issue((kc+1)*32, (kc+1)&1);
            asm volatile("cp.async.wait_group 1;");
        } else {
            asm volatile("cp.async.wait_group 0;");
        }
        __syncthreads();
        const __half2* A2 = (const __half2*)As[kc&1];
        const __half2* B2 = (const __half2*)Bs[kc&1];
#pragma unroll
        for (int ks = 0; ks < 2; ks++) {
            const int k2b = ks*8;
            uint32_t a[2][4], b[8][2];
#pragma unroll
            for (int i = 0; i < 2; i++) {
                int r = wm0 + i*16 + gid;
                a[i][0] = *(const uint32_t*)&A2[r*20 + k2b + tig];
                a[i][1] = *(const uint32_t*)&A2[(r+8)*20 + k2b + tig];
                a[i][2] = *(const uint32_t*)&A2[r*20 + k2b + tig + 4];
                a[i][3] = *(const uint32_t*)&A2[(r+8)*20 + k2b + tig + 4];
            }
#pragma unroll
            for (int j = 0; j < 8; j++) {
                int rn = wn0 + j*8 + gid;
                b[j][0] = *(const uint32_t*)&B2[rn*20 + k2b + tig];
                b[j][1] = *(const uint32_t*)&B2[rn*20 + k2b + tig + 4];
            }
#pragma unroll
            for (int i = 0; i < 2; i++)
#pragma unroll
                for (int j = 0; j < 8; j++)
                    asm volatile(
                        "mma.sync.aligned.m16n8k16.row.col.f32.f16.f16.f32 "
                        "{%0,%1,%2,%3}, {%4,%5,%6,%7}, {%8,%9}, {%0,%1,%2,%3};"
                        : "+f"(acc[i][j][0]), "+f"(acc[i][j][1]),
                          "+f"(acc[i][j][2]), "+f"(acc[i][j][3])
                        : "r"(a[i][0]), "r"(a[i][1]), "r"(a[i][2]), "r"(a[i][3]),
                          "r"(b[j][0]), "r"(b[j][1]));
        }
        __syncthreads();
    }
#pragma unroll
    for (int i = 0; i < 2; i++) {
        int row = m0 + wm0 + i*16 + gid;
#pragma unroll
        for (int j = 0; j < 8; j++) {
            int col = n0 + wn0 + j*8 + tig*2;
            *(float2*)(C + (size_t)row*Ng + col)     = make_float2(acc[i][j][0], acc[i][j][1]);
            *(float2*)(C + (size_t)(row+8)*Ng + col) = make_float2(acc[i][j][2], acc[i][j][3]);
        }
    }
}

// ---------------- per-sequence fused middle ----------------
// float-index map (fp32 arrays) + half-index map (fp16 arrays).
#define S_XM   0        // [16][256] fp32 x_m ; later HT [i][s] stride 17 (4352 f)
#define S_HT   0
// half arrays (indices in __half units)
#define H_XC   8704     // xc  [t][260]  (4160 h)
#define H_Q    12864    // q   [t][260]  (4160 h)
#define H_K    17024    // k   [t][260]  (4160 h)
#define H_V    21184    // v   [i][18]   (4608 h)
// float arrays resume (float units)
#define S_IG   12896    // [t][4]
#define S_FG   12960    // [t][4]
#define S_LFC  13024    // [h][17]
#define S_AA   13092    // [h][16]
#define H_WM   26312    // wm  [h][s][t] (1024 h)
#define SM3_FLOATS 13668   // 54.7 KB

__global__ void __launch_bounds__(256,4) k_seq(
    const float* __restrict__ UP,
    const float* __restrict__ conv_w, const float* __restrict__ conv_b,
    const float* __restrict__ Wq, const float* __restrict__ Wk, const float* __restrict__ Wv,
    const float* __restrict__ ig_w, const float* __restrict__ ig_b,
    const float* __restrict__ fg_w, const float* __restrict__ fg_b,
    const float* __restrict__ ln_w, const float* __restrict__ skip,
    __half* __restrict__ HS) {
    extern __shared__ float sm[];
    __half* smh = (__half*)sm;
    const int tid = threadIdx.x;
    const int seq = blockIdx.x;

    // --- A: load x_m [16][256] (first half of UP rows, fp32) ---
    {
        const float4* src = (const float4*)(UP + (size_t)seq * 16 * 512);
        float4* d4 = (float4*)(sm + S_XM);
        for (int i = tid; i < 1024; i += 256) {
            int row = i >> 6, q = i & 63;
            d4[row*64 + q] = src[row*128 + q];
        }
    }
    __syncthreads();

    // --- BC: fused conv+silu -> xc, then block-diagonal q,k,v ---
#pragma unroll
    for (int r = 0; r < 4; r++) {
        int e = tid + 256*r;          // 0..1023
        int t = e >> 6, n = e & 63;
        float4 a4 = *(const float4*)(conv_b + n*4);
#pragma unroll
        for (int j = 0; j < 4; j++) {
            int tt = t + j - 3;
            if (tt >= 0) {
                float4 cw = *(const float4*)(conv_w + j*256 + n*4);
                float4 xm = *(const float4*)&sm[S_XM + tt*256 + n*4];
                a4.x += cw.x*xm.x; a4.y += cw.y*xm.y;
                a4.z += cw.z*xm.z; a4.w += cw.w*xm.w;
            }
        }
        float4 xm_t = *(const float4*)&sm[S_XM + t*256 + n*4];
        float4 xc;
        xc.x = siluf(a4.x); xc.y = siluf(a4.y);
        xc.z = siluf(a4.z); xc.w = siluf(a4.w);
        *(__half2*)&smh[H_XC + t*260 + n*4]     = __float22half2_rn(make_float2(xc.x, xc.y));
        *(__half2*)&smh[H_XC + t*260 + n*4 + 2] = __float22half2_rn(make_float2(xc.z, xc.w));
        float qv[4], kv[4], vv[4];
#pragma unroll
        for (int o = 0; o < 4; o++) {
            float4 wq = *(const float4*)(Wq + n*16 + o*4);
            float4 wk = *(const float4*)(Wk + n*16 + o*4);
            float4 wv = *(const float4*)(Wv + n*16 + o*4);
            qv[o] = xc.x*wq.x + xc.y*wq.y + xc.z*wq.z + xc.w*wq.w;
            kv[o] = xc.x*wk.x + xc.y*wk.y + xc.z*wk.z + xc.w*wk.w;
            vv[o] = xm_t.x*wv.x + xm_t.y*wv.y + xm_t.z*wv.z + xm_t.w*wv.w;
        }
        *(__half2*)&smh[H_Q + t*260 + n*4]     = __float22half2_rn(make_float2(qv[0], qv[1]));
        *(__half2*)&smh[H_Q + t*260 + n*4 + 2] = __float22half2_rn(make_float2(qv[2], qv[3]));
        *(__half2*)&smh[H_K + t*260 + n*4]     = __float22half2_rn(make_float2(kv[0], kv[1]));
        *(__half2*)&smh[H_K + t*260 + n*4 + 2] = __float22half2_rn(make_float2(kv[2], kv[3]));
#pragma unroll
        for (int o = 0; o < 4; o++)
            smh[H_V + (n*4+o)*18 + t] = __float2half(vv[o]);
    }
    __syncthreads();

    // --- D: gate preacts; warp tp covers (t=tp, t=tp+8), lanes split j ---
    {
        const int gc = tid & 31;
        const int tp = tid >> 5;       // 0..7
        float aI0[4]={0,0,0,0}, aF0[4]={0,0,0,0};
        float aI1[4]={0,0,0,0}, aF1[4]={0,0,0,0};
#pragma unroll
        for (int i = 0; i < 8; i++) {   // q segment
            int jc = i*32 + gc, jj = jc;
            float v0 = __half2float(smh[H_Q + tp*260 + jc]);
            float v1 = __half2float(smh[H_Q + (tp+8)*260 + jc]);
            float4 wi = *(const float4*)(ig_w + jj*4);
            float4 wf = *(const float4*)(fg_w + jj*4);
            aI0[0]+=v0*wi.x; aI0[1]+=v0*wi.y; aI0[2]+=v0*wi.z; aI0[3]+=v0*wi.w;
            aF0[0]+=v0*wf.x; aF0[1]+=v0*wf.y; aF0[2]+=v0*wf.z; aF0[3]+=v0*wf.w;
            aI1[0]+=v1*wi.x; aI1[1]+=v1*wi.y; aI1[2]+=v1*wi.z; aI1[3]+=v1*wi.w;
            aF1[0]+=v1*wf.x; aF1[1]+=v1*wf.y; aF1[2]+=v1*wf.z; aF1[3]+=v1*wf.w;
        }
#pragma unroll
        for (int i = 0; i < 8; i++) {   // k segment
            int jc = i*32 + gc, jj = 256 + jc;
            float v0 = __half2float(smh[H_K + tp*260 + jc]);
            float v1 = __half2float(smh[H_K + (tp+8)*260 + jc]);
            float4 wi = *(const float4*)(ig_w + jj*4);
            float4 wf = *(const float4*)(fg_w + jj*4);
            aI0[0]+=v0*wi.x; aI0[1]+=v0*wi.y; aI0[2]+=v0*wi.z; aI0[3]+=v0*wi.w;
            aF0[0]+=v0*wf.x; aF0[1]+=v0*wf.y; aF0[2]+=v0*wf.z; aF0[3]+=v0*wf.w;
            aI1[0]+=v1*wi.x; aI1[1]+=v1*wi.y; aI1[2]+=v1*wi.z; aI1[3]+=v1*wi.w;
            aF1[0]+=v1*wf.x; aF1[1]+=v1*wf.y; aF1[2]+=v1*wf.z; aF1[3]+=v1*wf.w;
        }
#pragma unroll
        for (int i = 0; i < 8; i++) {   // v segment
            int jc = i*32 + gc, jj = 512 + jc;
            float v0 = __half2float(smh[H_V + jc*18 + tp]);
            float v1 = __half2float(smh[H_V + jc*18 + tp + 8]);
            float4 wi = *(const float4*)(ig_w + jj*4);
            float4 wf = *(const float4*)(fg_w + jj*4);
            aI0[0]+=v0*wi.x; aI0[1]+=v0*wi.y; aI0[2]+=v0*wi.z; aI0[3]+=v0*wi.w;
            aF0[0]+=v0*wf.x; aF0[1]+=v0*wf.y; aF0[2]+=v0*wf.z; aF0[3]+=v0*wf.w;
            aI1[0]+=v1*wi.x; aI1[1]+=v1*wi.y; aI1[2]+=v1*wi.z; aI1[3]+=v1*wi.w;
            aF1[0]+=v1*wf.x; aF1[1]+=v1*wf.y; aF1[2]+=v1*wf.z; aF1[3]+=v1*wf.w;
        }
#pragma unroll
        for (int m = 1; m < 32; m <<= 1) {
#pragma unroll
            for (int g = 0; g < 4; g++) {
                aI0[g] += __shfl_xor_sync(0xffffffffu, aI0[g], m);
                aF0[g] += __shfl_xor_sync(0xffffffffu, aF0[g], m);
                aI1[g] += __shfl_xor_sync(0xffffffffu, aI1[g], m);
                aF1[g] += __shfl_xor_sync(0xffffffffu, aF1[g], m);
            }
        }
        if (gc == 0) {
#pragma unroll
            for (int g = 0; g < 4; g++) {
                sm[S_IG + tp*4 + g]     = aI0[g] + ig_b[g];
                sm[S_FG + tp*4 + g]     = aF0[g] + fg_b[g];
                sm[S_IG + (tp+8)*4 + g] = aI1[g] + ig_b[g];
                sm[S_FG + (tp+8)*4 + g] = aF1[g] + fg_b[g];
            }
        }
    }
    __syncthreads();

    // --- E: parallel prefix scan of log-sigmoid(fg) (64 threads) ---
    if (tid < 64) {
        int h = tid >> 4, t = tid & 15;
        float fgv = sm[S_FG + t*4 + h];
        float cum = fminf(fgv, 0.f) - __logf(1.f + __expf(-fabsf(fgv)));
#pragma unroll
        for (int m = 1; m < 16; m <<= 1) {
            float o = __shfl_up_sync(0xffffffffu, cum, m, 16);
            if ((tid & 15) >= m) cum += o;
        }
        sm[S_LFC + h*17 + t + 1] = cum;
        if (t == 0) sm[S_LFC + h*17] = 0.f;
        sm[S_AA + h*16 + t] = sm[S_IG + t*4 + h] - cum;
    }
    // (no barrier yet; qk below only reads Q/K)

    // --- F1: qk (half2 over d) ---
    const int mh = tid >> 6;
    const int ms = (tid >> 2) & 15;
    const int mtq = tid & 3;
    float qkv4[4] = {0.f, 0.f, 0.f, 0.f};
    {
        int qb = H_Q + ms*260 + mh*64;
        int kb = H_K + mh*64;
#pragma unroll 8
        for (int dd = 0; dd < 32; dd++) {
            float2 qf = __half22float2(*(const __half2*)&smh[qb + 2*dd]);
#pragma unroll
            for (int j = 0; j < 4; j++) {
                int t = mtq*4 + j;
                float2 kf = __half22float2(*(const __half2*)&smh[kb + t*260 + 2*dd]);
                qkv4[j] += qf.x*kf.x + qf.y*kf.y;
            }
        }
    }
    __syncthreads();   // E results visible

    // --- F2: D-weights + normalizer -> wm (fp16) ---
    {
        float cs = sm[S_LFC + mh*17 + ms + 1];
        float mloc = -1e30f;
        float ldv[4];
#pragma unroll
        for (int j = 0; j < 4; j++) {
            int t = mtq*4 + j;
            if (t <= ms) { ldv[j] = cs + sm[S_AA + mh*16 + t]; mloc = fmaxf(mloc, ldv[j]); }
            else ldv[j] = 0.f;
        }
        mloc = fmaxf(mloc, __shfl_xor_sync(0xffffffffu, mloc, 1));
        mloc = fmaxf(mloc, __shfl_xor_sync(0xffffffffu, mloc, 2));
        float cv[4]; float csum = 0.f;
#pragma unroll
        for (int j = 0; j < 4; j++) {
            int t = mtq*4 + j;
            cv[j] = (t <= ms) ? (qkv4[j]*0.125f) * __expf(ldv[j] - mloc) : 0.f;
            csum += cv[j];
        }
        csum += __shfl_xor_sync(0xffffffffu, csum, 1);
        csum += __shfl_xor_sync(0xffffffffu, csum, 2);
        float norm = fmaxf(fabsf(csum), __expf(-mloc)) + 1e-6f;
        float inv = 1.f / norm;
        int wb = H_WM + (mh*16 + ms)*16 + mtq*4;
        *(__half2*)&smh[wb]     = __float22half2_rn(make_float2(cv[0]*inv, cv[1]*inv));
        *(__half2*)&smh[wb + 2] = __float22half2_rn(make_float2(cv[2]*inv, cv[3]*inv));
    }
    __syncthreads();

    // --- G: out = wm @ v -> HT (aliases dead XM) ---
    {
        int hC = tid >> 6, dC = tid & 63;
        int ib = H_V + (hC*64 + dC)*18;
        float vreg[16];
#pragma unroll
        for (int tp = 0; tp < 8; tp++) {
            float2 vf = __half22float2(*(const __half2*)&smh[ib + 2*tp]);
            vreg[2*tp] = vf.x; vreg[2*tp+1] = vf.y;
        }
#pragma unroll
        for (int s2 = 0; s2 < 16; s2++) {
            int wb = H_WM + (hC*16 + s2)*16;
            float a2 = 0.f;
#pragma unroll
            for (int tp = 0; tp < 8; tp++) {
                float2 wf = __half22float2(*(const __half2*)&smh[wb + 2*tp]);
                a2 += wf.x*vreg[2*tp] + wf.y*vreg[2*tp+1];
            }
            sm[S_HT + (hC*64 + dC)*17 + s2] = a2;
        }
    }
    __syncthreads();

    // --- H: group LayerNorm + skip*xc + silu(z) gate ---
    {
        int hD = tid >> 6, sD = (tid >> 2) & 15, dq = tid & 3;
        float vals[16]; float sum = 0.f, sq = 0.f;
#pragma unroll
        for (int dd = 0; dd < 16; dd++) {
            int i = hD*64 + dq*16 + dd;
            float v = sm[S_HT + i*17 + sD];
            vals[dd] = v; sum += v; sq += v*v;
        }
        sum += __shfl_xor_sync(0xffffffffu, sum, 1);
        sum += __shfl_xor_sync(0xffffffffu, sum, 2);
        sq  += __shfl_xor_sync(0xffffffffu, sq, 1);
        sq  += __shfl_xor_sync(0xffffffffu, sq, 2);
        float mu = sum * (1.f/64.f);
        float var = sq * (1.f/64.f) - mu*mu;
        float rstd = rsqrtf(var + 1e-5f);
        const float* zrow = UP + (size_t)seq*8192 + sD*512 + 256;
#pragma unroll
        for (int dd = 0; dd < 16; dd++) {
            int i = hD*64 + dq*16 + dd;
            float hn = (vals[dd] - mu) * rstd * ln_w[i];
            float zz = zrow[i];
            float xcv = __half2float(smh[H_XC + sD*260 + i]);
            float o = (hn + skip[i] * xcv) * siluf(zz);
            sm[S_HT + i*17 + sD] = o;
        }
    }
    __syncthreads();

    // --- coalesced write HS[row][i] (fp16) ---
    {
        __half2* dst = (__half2*)(HS + (size_t)seq * 16 * 256);
        for (int idx = tid; idx < 2048; idx += 256) {
            int t = idx >> 7, i2 = idx & 127;
            float v0 = sm[S_HT + (2*i2)*17 + t];
            float v1 = sm[S_HT + (2*i2+1)*17 + t];
            dst[idx] = __float22half2_rn(make_float2(v0, v1));
        }
    }
}

// ---------------- launch ----------------
extern "C" void kernel_launch(void* const* d_in, const int* in_sizes, int n_in,
                              void* d_out, int out_size) {
    const float* x      = (const float*)d_in[0];
    const float* W_up   = (const float*)d_in[1];
    const float* conv_w = (const float*)d_in[2];
    const float* conv_b = (const float*)d_in[3];
    const float* Wq     = (const float*)d_in[4];
    const float* Wk     = (const float*)d_in[5];
    const float* Wv     = (const float*)d_in[6];
    const float* ig_w   = (const float*)d_in[7];
    const float* ig_b   = (const float*)d_in[8];
    const float* fg_w   = (const float*)d_in[9];
    const float* fg_b   = (const float*)d_in[10];
    const float* ln_w   = (const float*)d_in[11];
    const float* skip   = (const float*)d_in[12];
    const float* W_down = (const float*)d_in[13];
    float* out = (float*)d_out;

    __half *XS, *HS, *WTU, *WTD;
    float *UP, *OT;
    cudaGetSymbolAddress((void**)&XS,  g_XS);
    cudaGetSymbolAddress((void**)&UP,  g_UP);
    cudaGetSymbolAddress((void**)&HS,  g_HS);
    cudaGetSymbolAddress((void**)&OT,  g_OT);
    cudaGetSymbolAddress((void**)&WTU, g_WTU);
    cudaGetSymbolAddress((void**)&WTD, g_WTD);

    cudaFuncSetAttribute(k_seq, cudaFuncAttributeMaxDynamicSharedMemorySize,
                         SM3_FLOATS * (int)sizeof(float));

    k_transpose_in<<<4096, 256>>>(x, XS);
    k_wt<<<256, 256>>>(W_up, WTU, 128, 512);
    k_wt<<<128, 256>>>(W_down, WTD, 256, 128);
    // up: C[131072,512] = XS[131072,128] @ WTU[512,128]^T
    k_gemm_h<<<dim3(4, 1024), 256>>>(XS, WTU, UP, 512, 128);
    k_seq<<<SEQS, 256, SM3_FLOATS * sizeof(float)>>>(UP, conv_w, conv_b,
        Wq, Wk, Wv, ig_w, ig_b, fg_w, fg_b, ln_w, skip, HS);
    // down: C[131072,128] = HS[131072,256] @ WTD[128,256]^T
    k_gemm_h<<<dim3(1, 1024), 256>>>(HS, WTD, OT, 128, 256);
    k_transpose_out<<<4096, 256>>>(OT, out);
}

// round 9
// speedup vs baseline: 1.6338x; 1.6338x over previous
#include <cuda_runtime.h>
#include <cuda_fp16.h>
#include <cstdint>
#include <math.h>

// ---------------- problem constants ----------------
#define DIMC  128
#define TT    16
#define INNER 256
#define SEQS  8192
#define ROWS  (SEQS*TT)         // 131072
#define UPCOLS 512

// ---------------- scratch (static device, no allocs) ----------------
__device__ __half g_XS[(size_t)ROWS*DIMC];   // [row][128] fp16
__device__ float  g_UP[(size_t)ROWS*UPCOLS]; // [row][512] fp32
__device__ __half g_HS[(size_t)ROWS*INNER];  // [row][256] fp16
__device__ float  g_OT[(size_t)ROWS*DIMC];   // [row][128] fp32
__device__ __half g_WTU[512*128];            // W_up^T  [n][k] fp16
__device__ __half g_WTD[128*256];            // W_down^T [n][k] fp16
__device__ __half g_GW[768*8];               // packed gate weights [j][ig0..3,fg0..3]

// ---------------- helpers ----------------
__device__ __forceinline__ float siluf(float x){ return x / (1.f + __expf(-x)); }
__device__ __forceinline__ uint32_t smem_u32(const void* p){
    uint32_t a;
    asm("{ .reg .u64 t; cvta.to.shared.u64 t, %1; cvt.u32.u64 %0, t; }" : "=r"(a) : "l"(p));
    return a;
}

// ---------------- kernel: (b,c,t,h,w) -> XS[seq][t][c] (fp16) ----------------
__global__ void __launch_bounds__(256) k_transpose_in(const float* __restrict__ x,
                                                      __half* __restrict__ XS) {
    __shared__ float tile[128*33];
    int bid = blockIdx.x;
    int b = bid >> 9;
    int t = (bid >> 5) & 15;
    int h = bid & 31;
    const float* src = x + ((size_t)(b*128)*16 + t) * 1024 + h*32;
    for (int idx = threadIdx.x; idx < 128*32; idx += 256) {
        int c = idx >> 5, w = idx & 31;
        tile[c*33 + w] = src[(size_t)c*16384 + w];
    }
    __syncthreads();
    size_t base = ((size_t)(b*1024 + h*32) * 16 + t) * 128;
    for (int idx = threadIdx.x; idx < 2048; idx += 256) {
        int w = idx >> 6, c2 = idx & 63;
        __half2 v = __float22half2_rn(make_float2(tile[(2*c2)*33 + w],
                                                  tile[(2*c2+1)*33 + w]));
        *(__half2*)(XS + base + (size_t)w*2048 + 2*c2) = v;
    }
}

// ---------------- kernel: OT[row][c] -> out (b,c,t,h,w) ----------------
__global__ void __launch_bounds__(256) k_transpose_out(const float* __restrict__ OT,
                                                       float* __restrict__ out) {
    __shared__ float tile[128*33];
    int bid = blockIdx.x;
    int b = bid >> 9;
    int t = (bid >> 5) & 15;
    int h = bid & 31;
    size_t base = ((size_t)(b*1024 + h*32) * 16 + t) * 128;
    for (int idx = threadIdx.x; idx < 32*128; idx += 256) {
        int w = idx >> 7, c = idx & 127;
        tile[c*33 + w] = OT[base + (size_t)w*2048 + c];
    }
    __syncthreads();
    float* dst = out + ((size_t)(b*128)*16 + t) * 1024 + h*32;
    for (int idx = threadIdx.x; idx < 128*32; idx += 256) {
        int c = idx >> 5, w = idx & 31;
        dst[(size_t)c*16384 + w] = tile[c*33 + w];
    }
}

// ---------------- weight transpose to fp16: Wt[n][k] = W[k][n] ----------------
__global__ void k_wt(const float* __restrict__ W, __half* __restrict__ Wt, int K, int N){
    int idx = blockIdx.x*256 + threadIdx.x;
    if (idx < K*N) { int k = idx / N, n = idx - k*N; Wt[(size_t)n*K + k] = __float2half(W[idx]); }
}

// ---------------- pack gate weights: GW[j][0..3]=ig_w[j][:], [4..7]=fg_w[j][:] ----------------
__global__ void k_gw(const float* __restrict__ ig_w, const float* __restrict__ fg_w,
                     __half* __restrict__ GW){
    int idx = blockIdx.x*256 + threadIdx.x;    // 0..6143
    if (idx < 6144) {
        int j = idx >> 3, g = idx & 7;
        float v = (g < 4) ? ig_w[j*4 + g] : fg_w[j*4 + (g-4)];
        GW[idx] = __float2half(v);
    }
}

// ---------------- fp16 warp-MMA GEMM: C[M,Ng] = A[M,K] @ Bt[Ng,K]^T ----------------
__global__ void __launch_bounds__(256) k_gemm_h(const __half* __restrict__ A,
        const __half* __restrict__ Bt, float* __restrict__ C, int Ng, int Kf) {
    __shared__ __align__(16) __half As[2][128*40];
    __shared__ __align__(16) __half Bs[2][128*40];
    const int tid  = threadIdx.x;
    const int lane = tid & 31, warp = tid >> 5;
    const int gid  = lane >> 2, tig = lane & 3;
    const int wm0  = (warp >> 1) * 32;
    const int wn0  = (warp & 1) * 64;
    const int m0 = blockIdx.y * 128, n0 = blockIdx.x * 128;
    const int nk = Kf >> 5;

    uint32_t sA0 = smem_u32(As[0]), sA1 = smem_u32(As[1]);
    uint32_t sB0 = smem_u32(Bs[0]), sB1 = smem_u32(Bs[1]);

    float acc[2][8][4];
#pragma unroll
    for (int i = 0; i < 2; i++)
#pragma unroll
        for (int j = 0; j < 8; j++)
#pragma unroll
            for (int e = 0; e < 4; e++) acc[i][j][e] = 0.f;

    auto issue = [&](int kb, int buf){
        uint32_t da_base = buf ? sA1 : sA0;
        uint32_t db_base = buf ? sB1 : sB0;
#pragma unroll
        for (int r = 0; r < 2; r++) {
            int idx = tid + 256*r;
            int row = idx >> 2, c16 = idx & 3;
            const __half* ga = A  + (size_t)(m0+row)*Kf + kb + c16*8;
            const __half* gb = Bt + (size_t)(n0+row)*Kf + kb + c16*8;
            uint32_t da = da_base + row*80 + c16*16;
            uint32_t db = db_base + row*80 + c16*16;
            asm volatile("cp.async.cg.shared.global [%0], [%1], 16;" :: "r"(da), "l"(ga));
            asm volatile("cp.async.cg.shared.global [%0], [%1], 16;" :: "r"(db), "l"(gb));
        }
        asm volatile("cp.async.commit_group;");
    };

    issue(0, 0);
    for (int kc = 0; kc < nk; kc++) {
        if (kc + 1 < nk) {
            issue((kc+1)*32, (kc+1)&1);
            asm volatile("cp.async.wait_group 1;");
        } else {
            asm volatile("cp.async.wait_group 0;");
        }
        __syncthreads();
        const __half2* A2 = (const __half2*)As[kc&1];
        const __half2* B2 = (const __half2*)Bs[kc&1];
#pragma unroll
        for (int ks = 0; ks < 2; ks++) {
            const int k2b = ks*8;
            uint32_t a[2][4], b[8][2];
#pragma unroll
            for (int i = 0; i < 2; i++) {
                int r = wm0 + i*16 + gid;
                a[i][0] = *(const uint32_t*)&A2[r*20 + k2b + tig];
                a[i][1] = *(const uint32_t*)&A2[(r+8)*20 + k2b + tig];
                a[i][2] = *(const uint32_t*)&A2[r*20 + k2b + tig + 4];
                a[i][3] = *(const uint32_t*)&A2[(r+8)*20 + k2b + tig + 4];
            }
#pragma unroll
            for (int j = 0; j < 8; j++) {
                int rn = wn0 + j*8 + gid;
                b[j][0] = *(const uint32_t*)&B2[rn*20 + k2b + tig];
                b[j][1] = *(const uint32_t*)&B2[rn*20 + k2b + tig + 4];
            }
#pragma unroll
            for (int i = 0; i < 2; i++)
#pragma unroll
                for (int j = 0; j < 8; j++)
                    asm volatile(
                        "mma.sync.aligned.m16n8k16.row.col.f32.f16.f16.f32 "
                        "{%0,%1,%2,%3}, {%4,%5,%6,%7}, {%8,%9}, {%0,%1,%2,%3};"
                        : "+f"(acc[i][j][0]), "+f"(acc[i][j][1]),
                          "+f"(acc[i][j][2]), "+f"(acc[i][j][3])
                        : "r"(a[i][0]), "r"(a[i][1]), "r"(a[i][2]), "r"(a[i][3]),
                          "r"(b[j][0]), "r"(b[j][1]));
        }
        __syncthreads();
    }
#pragma unroll
    for (int i = 0; i < 2; i++) {
        int row = m0 + wm0 + i*16 + gid;
#pragma unroll
        for (int j = 0; j < 8; j++) {
            int col = n0 + wn0 + j*8 + tig*2;
            *(float2*)(C + (size_t)row*Ng + col)     = make_float2(acc[i][j][0], acc[i][j][1]);
            *(float2*)(C + (size_t)(row+8)*Ng + col) = make_float2(acc[i][j][2], acc[i][j][3]);
        }
    }
}

// ---------------- per-sequence fused middle ----------------
// float-index map (fp32 arrays) + half-index map (fp16 arrays).
#define S_XM   0        // [16][256] fp32 x_m ; later HT [i][s] stride 17 (4352 f)
#define S_HT   0
// half arrays (indices in __half units)
#define H_XC   8704     // xc  [t][260]  (4160 h)
#define H_Q    12864    // q   [t][260]  (4160 h)
#define H_K    17024    // k   [t][260]  (4160 h)
#define H_V    21184    // v   [i][18]   (4608 h)
#define H_GW   25792    // gate weights [768][8] (6144 h), 16B-aligned
#define H_WM   31936    // wm  [h][s][t] (1024 h)
// float arrays resume (float units)
#define S_IG   16480    // [t][4]
#define S_FG   16544    // [t][4]
#define S_LFC  16608    // [h][17]
#define S_AA   16676    // [h][16]
#define SM3_FLOATS 16740   // 66.96 KB

__global__ void __launch_bounds__(256,3) k_seq(
    const float* __restrict__ UP,
    const float* __restrict__ conv_w, const float* __restrict__ conv_b,
    const float* __restrict__ Wq, const float* __restrict__ Wk, const float* __restrict__ Wv,
    const __half* __restrict__ GW,
    const float* __restrict__ ig_b, const float* __restrict__ fg_b,
    const float* __restrict__ ln_w, const float* __restrict__ skip,
    __half* __restrict__ HS) {
    extern __shared__ float sm[];
    __half* smh = (__half*)sm;
    const int tid = threadIdx.x;
    const int seq = blockIdx.x;

    // --- A: load x_m [16][256] (fp32) + packed gate weights into smem ---
    {
        const float4* src = (const float4*)(UP + (size_t)seq * 16 * 512);
        float4* d4 = (float4*)(sm + S_XM);
        for (int i = tid; i < 1024; i += 256) {
            int row = i >> 6, q = i & 63;
            d4[row*64 + q] = src[row*128 + q];
        }
        const uint4* gsrc = (const uint4*)GW;
        uint4* gdst = (uint4*)&smh[H_GW];
#pragma unroll
        for (int r = 0; r < 3; r++) gdst[tid + 256*r] = gsrc[tid + 256*r];
    }
    __syncthreads();

    // --- BC: fused conv+silu -> xc, then block-diagonal q,k,v ---
#pragma unroll
    for (int r = 0; r < 4; r++) {
        int e = tid + 256*r;          // 0..1023
        int t = e >> 6, n = e & 63;
        float4 a4 = *(const float4*)(conv_b + n*4);
#pragma unroll
        for (int j = 0; j < 4; j++) {
            int tt = t + j - 3;
            if (tt >= 0) {
                float4 cw = *(const float4*)(conv_w + j*256 + n*4);
                float4 xm = *(const float4*)&sm[S_XM + tt*256 + n*4];
                a4.x += cw.x*xm.x; a4.y += cw.y*xm.y;
                a4.z += cw.z*xm.z; a4.w += cw.w*xm.w;
            }
        }
        float4 xm_t = *(const float4*)&sm[S_XM + t*256 + n*4];
        float4 xc;
        xc.x = siluf(a4.x); xc.y = siluf(a4.y);
        xc.z = siluf(a4.z); xc.w = siluf(a4.w);
        *(__half2*)&smh[H_XC + t*260 + n*4]     = __float22half2_rn(make_float2(xc.x, xc.y));
        *(__half2*)&smh[H_XC + t*260 + n*4 + 2] = __float22half2_rn(make_float2(xc.z, xc.w));
        float qv[4], kv[4], vv[4];
#pragma unroll
        for (int o = 0; o < 4; o++) {
            float4 wq = *(const float4*)(Wq + n*16 + o*4);
            float4 wk = *(const float4*)(Wk + n*16 + o*4);
            float4 wv = *(const float4*)(Wv + n*16 + o*4);
            qv[o] = xc.x*wq.x + xc.y*wq.y + xc.z*wq.z + xc.w*wq.w;
            kv[o] = xc.x*wk.x + xc.y*wk.y + xc.z*wk.z + xc.w*wk.w;
            vv[o] = xm_t.x*wv.x + xm_t.y*wv.y + xm_t.z*wv.z + xm_t.w*wv.w;
        }
        *(__half2*)&smh[H_Q + t*260 + n*4]     = __float22half2_rn(make_float2(qv[0], qv[1]));
        *(__half2*)&smh[H_Q + t*260 + n*4 + 2] = __float22half2_rn(make_float2(qv[2], qv[3]));
        *(__half2*)&smh[H_K + t*260 + n*4]     = __float22half2_rn(make_float2(kv[0], kv[1]));
        *(__half2*)&smh[H_K + t*260 + n*4 + 2] = __float22half2_rn(make_float2(kv[2], kv[3]));
#pragma unroll
        for (int o = 0; o < 4; o++)
            smh[H_V + (n*4+o)*18 + t] = __float2half(vv[o]);
    }
    __syncthreads();

    // --- D: gate preacts; warp tp covers (t=tp, t=tp+8); weights via one LDS.128/j ---
    {
        const int gc = tid & 31;
        const int tp = tid >> 5;       // 0..7
        float aI0[4]={0,0,0,0}, aF0[4]={0,0,0,0};
        float aI1[4]={0,0,0,0}, aF1[4]={0,0,0,0};
#pragma unroll
        for (int seg = 0; seg < 3; seg++) {
#pragma unroll
            for (int i = 0; i < 8; i++) {
                int jc = i*32 + gc;
                int jj = seg*256 + jc;
                float v0, v1;
                if (seg == 0) {
                    v0 = __half2float(smh[H_Q + tp*260 + jc]);
                    v1 = __half2float(smh[H_Q + (tp+8)*260 + jc]);
                } else if (seg == 1) {
                    v0 = __half2float(smh[H_K + tp*260 + jc]);
                    v1 = __half2float(smh[H_K + (tp+8)*260 + jc]);
                } else {
                    v0 = __half2float(smh[H_V + jc*18 + tp]);
                    v1 = __half2float(smh[H_V + jc*18 + tp + 8]);
                }
                uint4 wraw = *(const uint4*)&smh[H_GW + jj*8];
                const __half2* wh = (const __half2*)&wraw;
                float2 i01 = __half22float2(wh[0]);
                float2 i23 = __half22float2(wh[1]);
                float2 f01 = __half22float2(wh[2]);
                float2 f23 = __half22float2(wh[3]);
                aI0[0]+=v0*i01.x; aI0[1]+=v0*i01.y; aI0[2]+=v0*i23.x; aI0[3]+=v0*i23.y;
                aF0[0]+=v0*f01.x; aF0[1]+=v0*f01.y; aF0[2]+=v0*f23.x; aF0[3]+=v0*f23.y;
                aI1[0]+=v1*i01.x; aI1[1]+=v1*i01.y; aI1[2]+=v1*i23.x; aI1[3]+=v1*i23.y;
                aF1[0]+=v1*f01.x; aF1[1]+=v1*f01.y; aF1[2]+=v1*f23.x; aF1[3]+=v1*f23.y;
            }
        }
#pragma unroll
        for (int m = 1; m < 32; m <<= 1) {
#pragma unroll
            for (int g = 0; g < 4; g++) {
                aI0[g] += __shfl_xor_sync(0xffffffffu, aI0[g], m);
                aF0[g] += __shfl_xor_sync(0xffffffffu, aF0[g], m);
                aI1[g] += __shfl_xor_sync(0xffffffffu, aI1[g], m);
                aF1[g] += __shfl_xor_sync(0xffffffffu, aF1[g], m);
            }
        }
        if (gc == 0) {
#pragma unroll
            for (int g = 0; g < 4; g++) {
                sm[S_IG + tp*4 + g]     = aI0[g] + ig_b[g];
                sm[S_FG + tp*4 + g]     = aF0[g] + fg_b[g];
                sm[S_IG + (tp+8)*4 + g] = aI1[g] + ig_b[g];
                sm[S_FG + (tp+8)*4 + g] = aF1[g] + fg_b[g];
            }
        }
    }
    __syncthreads();

    // --- E: parallel prefix scan of log-sigmoid(fg) (64 threads) ---
    if (tid < 64) {
        int h = tid >> 4, t = tid & 15;
        float fgv = sm[S_FG + t*4 + h];
        float cum = fminf(fgv, 0.f) - __logf(1.f + __expf(-fabsf(fgv)));
#pragma unroll
        for (int m = 1; m < 16; m <<= 1) {
            float o = __shfl_up_sync(0xffffffffu, cum, m, 16);
            if ((tid & 15) >= m) cum += o;
        }
        sm[S_LFC + h*17 + t + 1] = cum;
        if (t == 0) sm[S_LFC + h*17] = 0.f;
        sm[S_AA + h*16 + t] = sm[S_IG + t*4 + h] - cum;
    }
    // (no barrier yet; qk below only reads Q/K)

    // --- F1: qk (half2 over d) ---
    const int mh = tid >> 6;
    const int ms = (tid >> 2) & 15;
    const int mtq = tid & 3;
    float qkv4[4] = {0.f, 0.f, 0.f, 0.f};
    {
        int qb = H_Q + ms*260 + mh*64;
        int kb = H_K + mh*64;
#pragma unroll 8
        for (int dd = 0; dd < 32; dd++) {
            float2 qf = __half22float2(*(const __half2*)&smh[qb + 2*dd]);
#pragma unroll
            for (int j = 0; j < 4; j++) {
                int t = mtq*4 + j;
                float2 kf = __half22float2(*(const __half2*)&smh[kb + t*260 + 2*dd]);
                qkv4[j] += qf.x*kf.x + qf.y*kf.y;
            }
        }
    }
    __syncthreads();   // E results visible

    // --- F2: D-weights + normalizer -> wm (fp16) ---
    {
        float cs = sm[S_LFC + mh*17 + ms + 1];
        float mloc = -1e30f;
        float ldv[4];
#pragma unroll
        for (int j = 0; j < 4; j++) {
            int t = mtq*4 + j;
            if (t <= ms) { ldv[j] = cs + sm[S_AA + mh*16 + t]; mloc = fmaxf(mloc, ldv[j]); }
            else ldv[j] = 0.f;
        }
        mloc = fmaxf(mloc, __shfl_xor_sync(0xffffffffu, mloc, 1));
        mloc = fmaxf(mloc, __shfl_xor_sync(0xffffffffu, mloc, 2));
        float cv[4]; float csum = 0.f;
#pragma unroll
        for (int j = 0; j < 4; j++) {
            int t = mtq*4 + j;
            cv[j] = (t <= ms) ? (qkv4[j]*0.125f) * __expf(ldv[j] - mloc) : 0.f;
            csum += cv[j];
        }
        csum += __shfl_xor_sync(0xffffffffu, csum, 1);
        csum += __shfl_xor_sync(0xffffffffu, csum, 2);
        float norm = fmaxf(fabsf(csum), __expf(-mloc)) + 1e-6f;
        float inv = 1.f / norm;
        int wb = H_WM + (mh*16 + ms)*16 + mtq*4;
        *(__half2*)&smh[wb]     = __float22half2_rn(make_float2(cv[0]*inv, cv[1]*inv));
        *(__half2*)&smh[wb + 2] = __float22half2_rn(make_float2(cv[2]*inv, cv[3]*inv));
    }
    __syncthreads();

    // --- G: out = wm @ v -> HT (aliases dead XM) ---
    {
        int hC = tid >> 6, dC = tid & 63;
        int ib = H_V + (hC*64 + dC)*18;
        float vreg[16];
#pragma unroll
        for (int tp = 0; tp < 8; tp++) {
            float2 vf = __half22float2(*(const __half2*)&smh[ib + 2*tp]);
            vreg[2*tp] = vf.x; vreg[2*tp+1] = vf.y;
        }
#pragma unroll
        for (int s2 = 0; s2 < 16; s2++) {
            int wb = H_WM + (hC*16 + s2)*16;
            float a2 = 0.f;
#pragma unroll
            for (int tp = 0; tp < 8; tp++) {
                float2 wf = __half22float2(*(const __half2*)&smh[wb + 2*tp]);
                a2 += wf.x*vreg[2*tp] + wf.y*vreg[2*tp+1];
            }
            sm[S_HT + (hC*64 + dC)*17 + s2] = a2;
        }
    }
    __syncthreads();

    // --- H: group LayerNorm + skip*xc + silu(z) gate ---
    {
        int hD = tid >> 6, sD = (tid >> 2) & 15, dq = tid & 3;
        float vals[16]; float sum = 0.f, sq = 0.f;
#pragma unroll
        for (int dd = 0; dd < 16; dd++) {
            int i = hD*64 + dq*16 + dd;
            float v = sm[S_HT + i*17 + sD];
            vals[dd] = v; sum += v; sq += v*v;
        }
        sum += __shfl_xor_sync(0xffffffffu, sum, 1);
        sum += __shfl_xor_sync(0xffffffffu, sum, 2);
        sq  += __shfl_xor_sync(0xffffffffu, sq, 1);
        sq  += __shfl_xor_sync(0xffffffffu, sq, 2);
        float mu = sum * (1.f/64.f);
        float var = sq * (1.f/64.f) - mu*mu;
        float rstd = rsqrtf(var + 1e-5f);
        const float* zrow = UP + (size_t)seq*8192 + sD*512 + 256;
#pragma unroll
        for (int dd = 0; dd < 16; dd++) {
            int i = hD*64 + dq*16 + dd;
            float hn = (vals[dd] - mu) * rstd * ln_w[i];
            float zz = zrow[i];
            float xcv = __half2float(smh[H_XC + sD*260 + i]);
            float o = (hn + skip[i] * xcv) * siluf(zz);
            sm[S_HT + i*17 + sD] = o;
        }
    }
    __syncthreads();

    // --- coalesced write HS[row][i] (fp16) ---
    {
        __half2* dst = (__half2*)(HS + (size_t)seq * 16 * 256);
        for (int idx = tid; idx < 2048; idx += 256) {
            int t = idx >> 7, i2 = idx & 127;
            float v0 = sm[S_HT + (2*i2)*17 + t];
            float v1 = sm[S_HT + (2*i2+1)*17 + t];
            dst[idx] = __float22half2_rn(make_float2(v0, v1));
        }
    }
}

// ---------------- launch ----------------
extern "C" void kernel_launch(void* const* d_in, const int* in_sizes, int n_in,
                              void* d_out, int out_size) {
    const float* x      = (const float*)d_in[0];
    const float* W_up   = (const float*)d_in[1];
    const float* conv_w = (const float*)d_in[2];
    const float* conv_b = (const float*)d_in[3];
    const float* Wq     = (const float*)d_in[4];
    const float* Wk     = (const float*)d_in[5];
    const float* Wv     = (const float*)d_in[6];
    const float* ig_w   = (const float*)d_in[7];
    const float* ig_b   = (const float*)d_in[8];
    const float* fg_w   = (const float*)d_in[9];
    const float* fg_b   = (const float*)d_in[10];
    const float* ln_w   = (const float*)d_in[11];
    const float* skip   = (const float*)d_in[12];
    const float* W_down = (const float*)d_in[13];
    float* out = (float*)d_out;

    __half *XS, *HS, *WTU, *WTD, *GW;
    float *UP, *OT;
    cudaGetSymbolAddress((void**)&XS,  g_XS);
    cudaGetSymbolAddress((void**)&UP,  g_UP);
    cudaGetSymbolAddress((void**)&HS,  g_HS);
    cudaGetSymbolAddress((void**)&OT,  g_OT);
    cudaGetSymbolAddress((void**)&WTU, g_WTU);
    cudaGetSymbolAddress((void**)&WTD, g_WTD);
    cudaGetSymbolAddress((void**)&GW,  g_GW);

    cudaFuncSetAttribute(k_seq, cudaFuncAttributeMaxDynamicSharedMemorySize,
                         SM3_FLOATS * (int)sizeof(float));

    k_transpose_in<<<4096, 256>>>(x, XS);
    k_wt<<<256, 256>>>(W_up, WTU, 128, 512);
    k_wt<<<128, 256>>>(W_down, WTD, 256, 128);
    k_gw<<<24, 256>>>(ig_w, fg_w, GW);
    // up: C[131072,512] = XS[131072,128] @ WTU[512,128]^T
    k_gemm_h<<<dim3(4, 1024), 256>>>(XS, WTU, UP, 512, 128);
    k_seq<<<SEQS, 256, SM3_FLOATS * sizeof(float)>>>(UP, conv_w, conv_b,
        Wq, Wk, Wv, GW, ig_b, fg_b, ln_w, skip, HS);
    // down: C[131072,128] = HS[131072,256] @ WTD[128,256]^T
    k_gemm_h<<<dim3(1, 1024), 256>>>(HS, WTD, OT, 128, 256);
    k_transpose_out<<<4096, 256>>>(OT, out);
}

// round 10
// speedup vs baseline: 1.6855x; 1.0317x over previous
#include <cuda_runtime.h>
#include <cuda_fp16.h>
#include <cstdint>
#include <math.h>

// ---------------- problem constants ----------------
#define DIMC  128
#define TT    16
#define INNER 256
#define SEQS  8192
#define ROWS  (SEQS*TT)         // 131072
#define UPCOLS 512

// ---------------- scratch (static device, no allocs) ----------------
__device__ __half g_XS[(size_t)ROWS*DIMC];   // [row][128] fp16
__device__ __half g_UP[(size_t)ROWS*UPCOLS]; // [row][512] fp16
__device__ __half g_HS[(size_t)ROWS*INNER];  // [row][256] fp16
__device__ float  g_OT[(size_t)ROWS*DIMC];   // [row][128] fp32
__device__ __half g_WTU[512*128];            // W_up^T  [n][k] fp16
__device__ __half g_WTD[128*256];            // W_down^T [n][k] fp16
__device__ __half g_GW[768*8];               // packed gate weights [j][ig0..3,fg0..3]

// ---------------- helpers ----------------
__device__ __forceinline__ float siluf(float x){ return x / (1.f + __expf(-x)); }
__device__ __forceinline__ uint32_t smem_u32(const void* p){
    uint32_t a;
    asm("{ .reg .u64 t; cvta.to.shared.u64 t, %1; cvt.u32.u64 %0, t; }" : "=r"(a) : "l"(p));
    return a;
}

// ---------------- kernel: (b,c,t,h,w) -> XS[seq][t][c] (fp16) ----------------
__global__ void __launch_bounds__(256) k_transpose_in(const float* __restrict__ x,
                                                      __half* __restrict__ XS) {
    __shared__ float tile[128*33];
    int bid = blockIdx.x;
    int b = bid >> 9;
    int t = (bid >> 5) & 15;
    int h = bid & 31;
    const float* src = x + ((size_t)(b*128)*16 + t) * 1024 + h*32;
    for (int idx = threadIdx.x; idx < 128*32; idx += 256) {
        int c = idx >> 5, w = idx & 31;
        tile[c*33 + w] = src[(size_t)c*16384 + w];
    }
    __syncthreads();
    size_t base = ((size_t)(b*1024 + h*32) * 16 + t) * 128;
    for (int idx = threadIdx.x; idx < 2048; idx += 256) {
        int w = idx >> 6, c2 = idx & 63;
        __half2 v = __float22half2_rn(make_float2(tile[(2*c2)*33 + w],
                                                  tile[(2*c2+1)*33 + w]));
        *(__half2*)(XS + base + (size_t)w*2048 + 2*c2) = v;
    }
}

// ---------------- kernel: OT[row][c] -> out (b,c,t,h,w) ----------------
__global__ void __launch_bounds__(256) k_transpose_out(const float* __restrict__ OT,
                                                       float* __restrict__ out) {
    __shared__ float tile[128*33];
    int bid = blockIdx.x;
    int b = bid >> 9;
    int t = (bid >> 5) & 15;
    int h = bid & 31;
    size_t base = ((size_t)(b*1024 + h*32) * 16 + t) * 128;
    for (int idx = threadIdx.x; idx < 32*128; idx += 256) {
        int w = idx >> 7, c = idx & 127;
        tile[c*33 + w] = OT[base + (size_t)w*2048 + c];
    }
    __syncthreads();
    float* dst = out + ((size_t)(b*128)*16 + t) * 1024 + h*32;
    for (int idx = threadIdx.x; idx < 128*32; idx += 256) {
        int c = idx >> 5, w = idx & 31;
        dst[(size_t)c*16384 + w] = tile[c*33 + w];
    }
}

// ---------------- merged prep: WTU, WTD, GW (one launch) ----------------
__global__ void k_prep(const float* __restrict__ W_up, const float* __restrict__ W_down,
                       const float* __restrict__ ig_w, const float* __restrict__ fg_w,
                       __half* __restrict__ WTU, __half* __restrict__ WTD,
                       __half* __restrict__ GW){
    int blk = blockIdx.x;
    if (blk < 256) {                                  // WTU: 128x512 -> [512][128]
        int idx = blk*256 + threadIdx.x;
        int k = idx >> 9, n = idx & 511;
        WTU[(size_t)n*128 + k] = __float2half(W_up[idx]);
    } else if (blk < 384) {                           // WTD: 256x128 -> [128][256]
        int idx = (blk-256)*256 + threadIdx.x;
        int k = idx >> 7, n = idx & 127;
        WTD[(size_t)n*256 + k] = __float2half(W_down[idx]);
    } else {                                          // GW pack
        int idx = (blk-384)*256 + threadIdx.x;        // 0..6143
        if (idx < 6144) {
            int j = idx >> 3, g = idx & 7;
            float v = (g < 4) ? ig_w[j*4 + g] : fg_w[j*4 + (g-4)];
            GW[idx] = __float2half(v);
        }
    }
}

// ---------------- fp16 warp-MMA GEMM: C[M,Ng] = A[M,K] @ Bt[Ng,K]^T ----------------
template<bool HOUT>
__global__ void __launch_bounds__(256) k_gemm_h(const __half* __restrict__ A,
        const __half* __restrict__ Bt, void* __restrict__ Cv, int Ng, int Kf) {
    __shared__ __align__(16) __half As[2][128*40];
    __shared__ __align__(16) __half Bs[2][128*40];
    const int tid  = threadIdx.x;
    const int lane = tid & 31, warp = tid >> 5;
    const int gid  = lane >> 2, tig = lane & 3;
    const int wm0  = (warp >> 1) * 32;
    const int wn0  = (warp & 1) * 64;
    const int m0 = blockIdx.y * 128, n0 = blockIdx.x * 128;
    const int nk = Kf >> 5;

    uint32_t sA0 = smem_u32(As[0]), sA1 = smem_u32(As[1]);
    uint32_t sB0 = smem_u32(Bs[0]), sB1 = smem_u32(Bs[1]);

    float acc[2][8][4];
#pragma unroll
    for (int i = 0; i < 2; i++)
#pragma unroll
        for (int j = 0; j < 8; j++)
#pragma unroll
            for (int e = 0; e < 4; e++) acc[i][j][e] = 0.f;

    auto issue = [&](int kb, int buf){
        uint32_t da_base = buf ? sA1 : sA0;
        uint32_t db_base = buf ? sB1 : sB0;
#pragma unroll
        for (int r = 0; r < 2; r++) {
            int idx = tid + 256*r;
            int row = idx >> 2, c16 = idx & 3;
            const __half* ga = A  + (size_t)(m0+row)*Kf + kb + c16*8;
            const __half* gb = Bt + (size_t)(n0+row)*Kf + kb + c16*8;
            uint32_t da = da_base + row*80 + c16*16;
            uint32_t db = db_base + row*80 + c16*16;
            asm volatile("cp.async.cg.shared.global [%0], [%1], 16;" :: "r"(da), "l"(ga));
            asm volatile("cp.async.cg.shared.global [%0], [%1], 16;" :: "r"(db), "l"(gb));
        }
        asm volatile("cp.async.commit_group;");
    };

    issue(0, 0);
    for (int kc = 0; kc < nk; kc++) {
        if (kc + 1 < nk) {
            issue((kc+1)*32, (kc+1)&1);
            asm volatile("cp.async.wait_group 1;");
        } else {
            asm volatile("cp.async.wait_group 0;");
        }
        __syncthreads();
        const __half2* A2 = (const __half2*)As[kc&1];
        const __half2* B2 = (const __half2*)Bs[kc&1];
#pragma unroll
        for (int ks = 0; ks < 2; ks++) {
            const int k2b = ks*8;
            uint32_t a[2][4], b[8][2];
#pragma unroll
            for (int i = 0; i < 2; i++) {
                int r = wm0 + i*16 + gid;
                a[i][0] = *(const uint32_t*)&A2[r*20 + k2b + tig];
                a[i][1] = *(const uint32_t*)&A2[(r+8)*20 + k2b + tig];
                a[i][2] = *(const uint32_t*)&A2[r*20 + k2b + tig + 4];
                a[i][3] = *(const uint32_t*)&A2[(r+8)*20 + k2b + tig + 4];
            }
#pragma unroll
            for (int j = 0; j < 8; j++) {
                int rn = wn0 + j*8 + gid;
                b[j][0] = *(const uint32_t*)&B2[rn*20 + k2b + tig];
                b[j][1] = *(const uint32_t*)&B2[rn*20 + k2b + tig + 4];
            }
#pragma unroll
            for (int i = 0; i < 2; i++)
#pragma unroll
                for (int j = 0; j < 8; j++)
                    asm volatile(
                        "mma.sync.aligned.m16n8k16.row.col.f32.f16.f16.f32 "
                        "{%0,%1,%2,%3}, {%4,%5,%6,%7}, {%8,%9}, {%0,%1,%2,%3};"
                        : "+f"(acc[i][j][0]), "+f"(acc[i][j][1]),
                          "+f"(acc[i][j][2]), "+f"(acc[i][j][3])
                        : "r"(a[i][0]), "r"(a[i][1]), "r"(a[i][2]), "r"(a[i][3]),
                          "r"(b[j][0]), "r"(b[j][1]));
        }
        __syncthreads();
    }
#pragma unroll
    for (int i = 0; i < 2; i++) {
        int row = m0 + wm0 + i*16 + gid;
#pragma unroll
        for (int j = 0; j < 8; j++) {
            int col = n0 + wn0 + j*8 + tig*2;
            if (HOUT) {
                __half* C = (__half*)Cv;
                *(__half2*)(C + (size_t)row*Ng + col) =
                    __float22half2_rn(make_float2(acc[i][j][0], acc[i][j][1]));
                *(__half2*)(C + (size_t)(row+8)*Ng + col) =
                    __float22half2_rn(make_float2(acc[i][j][2], acc[i][j][3]));
            } else {
                float* C = (float*)Cv;
                *(float2*)(C + (size_t)row*Ng + col)     = make_float2(acc[i][j][0], acc[i][j][1]);
                *(float2*)(C + (size_t)(row+8)*Ng + col) = make_float2(acc[i][j][2], acc[i][j][3]);
            }
        }
    }
}

// ---------------- per-sequence fused middle ----------------
// float-index map (fp32 arrays) + half-index map (fp16 arrays).
#define S_XM   0        // [16][256] fp32 x_m ; later HT [i][s] stride 17 (4352 f)
#define S_HT   0
// half arrays (indices in __half units); row stride 264 for 16B-aligned rows
#define H_XC   8704     // xc  [t][264]  (4224 h)
#define H_Q    12928    // q   [t][264]  (4224 h)
#define H_K    17152    // k   [t][264]  (4224 h)
#define H_V    21376    // v   [i][18]   (4608 h)
#define H_GW   25984    // gate weights [768][8] (6144 h)
#define H_WM   32128    // wm  [h][s][t] (1024 h)  ends 33152
// float arrays resume (float units): 33152/2 = 16576
#define S_IG   16576    // [t][4]
#define S_FG   16640    // [t][4]
#define S_LFC  16704    // [h][17]
#define S_AA   16772    // [h][16]
#define SM3_FLOATS 16840   // 67.36 KB

__global__ void __launch_bounds__(256,3) k_seq(
    const __half* __restrict__ UP,
    const float* __restrict__ conv_w, const float* __restrict__ conv_b,
    const float* __restrict__ Wq, const float* __restrict__ Wk, const float* __restrict__ Wv,
    const __half* __restrict__ GW,
    const float* __restrict__ ig_b, const float* __restrict__ fg_b,
    const float* __restrict__ ln_w, const float* __restrict__ skip,
    __half* __restrict__ HS) {
    extern __shared__ float sm[];
    __half* smh = (__half*)sm;
    const int tid = threadIdx.x;
    const int seq = blockIdx.x;

    // --- A: load x_m [16][256] (fp16 -> fp32 smem) + gate weights ---
    {
        const uint4* src = (const uint4*)(UP + (size_t)seq * 16 * 512);
#pragma unroll
        for (int rr = 0; rr < 2; rr++) {
            int i = tid + 256*rr;              // 0..511
            int row = i >> 5, q = i & 31;      // q-th uint4 (8 halfs)
            uint4 v = src[row*64 + q];
            const __half2* hp = (const __half2*)&v;
            float2 f0 = __half22float2(hp[0]);
            float2 f1 = __half22float2(hp[1]);
            float2 f2 = __half22float2(hp[2]);
            float2 f3 = __half22float2(hp[3]);
            float* dst = &sm[S_XM + row*256 + q*8];
            *(float4*)dst     = make_float4(f0.x, f0.y, f1.x, f1.y);
            *(float4*)(dst+4) = make_float4(f2.x, f2.y, f3.x, f3.y);
        }
        const uint4* gsrc = (const uint4*)GW;
        uint4* gdst = (uint4*)&smh[H_GW];
#pragma unroll
        for (int r = 0; r < 3; r++) gdst[tid + 256*r] = gsrc[tid + 256*r];
    }
    __syncthreads();

    // --- BC: fused conv+silu -> xc, then block-diagonal q,k,v (weights hoisted) ---
    {
        const int n = tid & 63;
        const int t0 = tid >> 6;
        float4 cw[4];
#pragma unroll
        for (int j = 0; j < 4; j++) cw[j] = *(const float4*)(conv_w + j*256 + n*4);
        const float4 cb = *(const float4*)(conv_b + n*4);
#pragma unroll
        for (int r = 0; r < 4; r++) {
            int t = t0 + r*4;
            float4 a4 = cb;
#pragma unroll
            for (int j = 0; j < 4; j++) {
                int tt = t + j - 3;
                if (tt >= 0) {
                    float4 xm = *(const float4*)&sm[S_XM + tt*256 + n*4];
                    a4.x += cw[j].x*xm.x; a4.y += cw[j].y*xm.y;
                    a4.z += cw[j].z*xm.z; a4.w += cw[j].w*xm.w;
                }
            }
            float4 xm_t = *(const float4*)&sm[S_XM + t*256 + n*4];
            float4 xc;
            xc.x = siluf(a4.x); xc.y = siluf(a4.y);
            xc.z = siluf(a4.z); xc.w = siluf(a4.w);
            *(__half2*)&smh[H_XC + t*264 + n*4]     = __float22half2_rn(make_float2(xc.x, xc.y));
            *(__half2*)&smh[H_XC + t*264 + n*4 + 2] = __float22half2_rn(make_float2(xc.z, xc.w));
            float qv[4], kv[4], vv[4];
#pragma unroll
            for (int o = 0; o < 4; o++) {
                float4 wq = *(const float4*)(Wq + n*16 + o*4);
                float4 wk = *(const float4*)(Wk + n*16 + o*4);
                float4 wv = *(const float4*)(Wv + n*16 + o*4);
                qv[o] = xc.x*wq.x + xc.y*wq.y + xc.z*wq.z + xc.w*wq.w;
                kv[o] = xc.x*wk.x + xc.y*wk.y + xc.z*wk.z + xc.w*wk.w;
                vv[o] = xm_t.x*wv.x + xm_t.y*wv.y + xm_t.z*wv.z + xm_t.w*wv.w;
            }
            *(__half2*)&smh[H_Q + t*264 + n*4]     = __float22half2_rn(make_float2(qv[0], qv[1]));
            *(__half2*)&smh[H_Q + t*264 + n*4 + 2] = __float22half2_rn(make_float2(qv[2], qv[3]));
            *(__half2*)&smh[H_K + t*264 + n*4]     = __float22half2_rn(make_float2(kv[0], kv[1]));
            *(__half2*)&smh[H_K + t*264 + n*4 + 2] = __float22half2_rn(make_float2(kv[2], kv[3]));
#pragma unroll
            for (int o = 0; o < 4; o++)
                smh[H_V + (n*4+o)*18 + t] = __float2half(vv[o]);
        }
    }
    __syncthreads();

    // --- D: gate preacts; warp tp covers (t=tp, t=tp+8); weights via one LDS.128/j ---
    {
        const int gc = tid & 31;
        const int tp = tid >> 5;       // 0..7
        float aI0[4]={0,0,0,0}, aF0[4]={0,0,0,0};
        float aI1[4]={0,0,0,0}, aF1[4]={0,0,0,0};
#pragma unroll
        for (int seg = 0; seg < 3; seg++) {
#pragma unroll
            for (int i = 0; i < 8; i++) {
                int jc = i*32 + gc;
                int jj = seg*256 + jc;
                float v0, v1;
                if (seg == 0) {
                    v0 = __half2float(smh[H_Q + tp*264 + jc]);
                    v1 = __half2float(smh[H_Q + (tp+8)*264 + jc]);
                } else if (seg == 1) {
                    v0 = __half2float(smh[H_K + tp*264 + jc]);
                    v1 = __half2float(smh[H_K + (tp+8)*264 + jc]);
                } else {
                    v0 = __half2float(smh[H_V + jc*18 + tp]);
                    v1 = __half2float(smh[H_V + jc*18 + tp + 8]);
                }
                uint4 wraw = *(const uint4*)&smh[H_GW + jj*8];
                const __half2* wh = (const __half2*)&wraw;
                float2 i01 = __half22float2(wh[0]);
                float2 i23 = __half22float2(wh[1]);
                float2 f01 = __half22float2(wh[2]);
                float2 f23 = __half22float2(wh[3]);
                aI0[0]+=v0*i01.x; aI0[1]+=v0*i01.y; aI0[2]+=v0*i23.x; aI0[3]+=v0*i23.y;
                aF0[0]+=v0*f01.x; aF0[1]+=v0*f01.y; aF0[2]+=v0*f23.x; aF0[3]+=v0*f23.y;
                aI1[0]+=v1*i01.x; aI1[1]+=v1*i01.y; aI1[2]+=v1*i23.x; aI1[3]+=v1*i23.y;
                aF1[0]+=v1*f01.x; aF1[1]+=v1*f01.y; aF1[2]+=v1*f23.x; aF1[3]+=v1*f23.y;
            }
        }
#pragma unroll
        for (int m = 1; m < 32; m <<= 1) {
#pragma unroll
            for (int g = 0; g < 4; g++) {
                aI0[g] += __shfl_xor_sync(0xffffffffu, aI0[g], m);
                aF0[g] += __shfl_xor_sync(0xffffffffu, aF0[g], m);
                aI1[g] += __shfl_xor_sync(0xffffffffu, aI1[g], m);
                aF1[g] += __shfl_xor_sync(0xffffffffu, aF1[g], m);
            }
        }
        if (gc == 0) {
#pragma unroll
            for (int g = 0; g < 4; g++) {
                sm[S_IG + tp*4 + g]     = aI0[g] + ig_b[g];
                sm[S_FG + tp*4 + g]     = aF0[g] + fg_b[g];
                sm[S_IG + (tp+8)*4 + g] = aI1[g] + ig_b[g];
                sm[S_FG + (tp+8)*4 + g] = aF1[g] + fg_b[g];
            }
        }
    }
    __syncthreads();

    // --- E: parallel prefix scan of log-sigmoid(fg) (64 threads) ---
    if (tid < 64) {
        int h = tid >> 4, t = tid & 15;
        float fgv = sm[S_FG + t*4 + h];
        float cum = fminf(fgv, 0.f) - __logf(1.f + __expf(-fabsf(fgv)));
#pragma unroll
        for (int m = 1; m < 16; m <<= 1) {
            float o = __shfl_up_sync(0xffffffffu, cum, m, 16);
            if ((tid & 15) >= m) cum += o;
        }
        sm[S_LFC + h*17 + t + 1] = cum;
        if (t == 0) sm[S_LFC + h*17] = 0.f;
        sm[S_AA + h*16 + t] = sm[S_IG + t*4 + h] - cum;
    }
    // (no barrier yet; qk below only reads Q/K)

    // --- F1: qk (LDS.128 over d) ---
    const int mh = tid >> 6;
    const int ms = (tid >> 2) & 15;
    const int mtq = tid & 3;
    float qkv4[4] = {0.f, 0.f, 0.f, 0.f};
    {
        int qb = H_Q + ms*264 + mh*64;
        int kb = H_K + mh*64;
#pragma unroll
        for (int d8 = 0; d8 < 8; d8++) {
            uint4 qr = *(const uint4*)&smh[qb + d8*8];
            const __half2* qh = (const __half2*)&qr;
            float2 qf[4];
#pragma unroll
            for (int u = 0; u < 4; u++) qf[u] = __half22float2(qh[u]);
#pragma unroll
            for (int j = 0; j < 4; j++) {
                int t = mtq*4 + j;
                uint4 kr = *(const uint4*)&smh[kb + t*264 + d8*8];
                const __half2* kh = (const __half2*)&kr;
#pragma unroll
                for (int u = 0; u < 4; u++) {
                    float2 kf = __half22float2(kh[u]);
                    qkv4[j] += qf[u].x*kf.x + qf[u].y*kf.y;
                }
            }
        }
    }
    __syncthreads();   // E results visible

    // --- F2: D-weights + normalizer -> wm (fp16) ---
    {
        float cs = sm[S_LFC + mh*17 + ms + 1];
        float mloc = -1e30f;
        float ldv[4];
#pragma unroll
        for (int j = 0; j < 4; j++) {
            int t = mtq*4 + j;
            if (t <= ms) { ldv[j] = cs + sm[S_AA + mh*16 + t]; mloc = fmaxf(mloc, ldv[j]); }
            else ldv[j] = 0.f;
        }
        mloc = fmaxf(mloc, __shfl_xor_sync(0xffffffffu, mloc, 1));
        mloc = fmaxf(mloc, __shfl_xor_sync(0xffffffffu, mloc, 2));
        float cv[4]; float csum = 0.f;
#pragma unroll
        for (int j = 0; j < 4; j++) {
            int t = mtq*4 + j;
            cv[j] = (t <= ms) ? (qkv4[j]*0.125f) * __expf(ldv[j] - mloc) : 0.f;
            csum += cv[j];
        }
        csum += __shfl_xor_sync(0xffffffffu, csum, 1);
        csum += __shfl_xor_sync(0xffffffffu, csum, 2);
        float norm = fmaxf(fabsf(csum), __expf(-mloc)) + 1e-6f;
        float inv = 1.f / norm;
        int wb = H_WM + (mh*16 + ms)*16 + mtq*4;
        *(__half2*)&smh[wb]     = __float22half2_rn(make_float2(cv[0]*inv, cv[1]*inv));
        *(__half2*)&smh[wb + 2] = __float22half2_rn(make_float2(cv[2]*inv, cv[3]*inv));
    }
    __syncthreads();

    // --- G: out = wm @ v -> HT (aliases dead XM) ---
    {
        int hC = tid >> 6, dC = tid & 63;
        int ib = H_V + (hC*64 + dC)*18;
        float vreg[16];
#pragma unroll
        for (int tp = 0; tp < 8; tp++) {
            float2 vf = __half22float2(*(const __half2*)&smh[ib + 2*tp]);
            vreg[2*tp] = vf.x; vreg[2*tp+1] = vf.y;
        }
#pragma unroll
        for (int s2 = 0; s2 < 16; s2++) {
            int wb = H_WM + (hC*16 + s2)*16;
            float a2 = 0.f;
#pragma unroll
            for (int tp = 0; tp < 8; tp++) {
                float2 wf = __half22float2(*(const __half2*)&smh[wb + 2*tp]);
                a2 += wf.x*vreg[2*tp] + wf.y*vreg[2*tp+1];
            }
            sm[S_HT + (hC*64 + dC)*17 + s2] = a2;
        }
    }
    __syncthreads();

    // --- H: group LayerNorm + skip*xc + silu(z) gate (z fp16, vectorized) ---
    {
        int hD = tid >> 6, sD = (tid >> 2) & 15, dq = tid & 3;
        float vals[16]; float sum = 0.f, sq = 0.f;
#pragma unroll
        for (int dd = 0; dd < 16; dd++) {
            int i = hD*64 + dq*16 + dd;
            float v = sm[S_HT + i*17 + sD];
            vals[dd] = v; sum += v; sq += v*v;
        }
        sum += __shfl_xor_sync(0xffffffffu, sum, 1);
        sum += __shfl_xor_sync(0xffffffffu, sum, 2);
        sq  += __shfl_xor_sync(0xffffffffu, sq, 1);
        sq  += __shfl_xor_sync(0xffffffffu, sq, 2);
        float mu = sum * (1.f/64.f);
        float var = sq * (1.f/64.f) - mu*mu;
        float rstd = rsqrtf(var + 1e-5f);
        int ib0 = hD*64 + dq*16;
        const __half* zrow = UP + (size_t)seq*8192 + sD*512 + 256 + ib0;
        uint4 zr0 = *(const uint4*)zrow;
        uint4 zr1 = *(const uint4*)(zrow + 8);
        float zz[16];
        {
            const __half2* z2 = (const __half2*)&zr0;
#pragma unroll
            for (int u = 0; u < 4; u++) {
                float2 f = __half22float2(z2[u]);
                zz[2*u] = f.x; zz[2*u+1] = f.y;
            }
            const __half2* z3 = (const __half2*)&zr1;
#pragma unroll
            for (int u = 0; u < 4; u++) {
                float2 f = __half22float2(z3[u]);
                zz[8+2*u] = f.x; zz[8+2*u+1] = f.y;
            }
        }
#pragma unroll
        for (int dd = 0; dd < 16; dd++) {
            int i = ib0 + dd;
            float hn = (vals[dd] - mu) * rstd * ln_w[i];
            float xcv = __half2float(smh[H_XC + sD*264 + i]);
            float o = (hn + skip[i] * xcv) * siluf(zz[dd]);
            sm[S_HT + i*17 + sD] = o;
        }
    }
    __syncthreads();

    // --- coalesced write HS[row][i] (fp16) ---
    {
        __half2* dst = (__half2*)(HS + (size_t)seq * 16 * 256);
        for (int idx = tid; idx < 2048; idx += 256) {
            int t = idx >> 7, i2 = idx & 127;
            float v0 = sm[S_HT + (2*i2)*17 + t];
            float v1 = sm[S_HT + (2*i2+1)*17 + t];
            dst[idx] = __float22half2_rn(make_float2(v0, v1));
        }
    }
}

// ---------------- launch ----------------
extern "C" void kernel_launch(void* const* d_in, const int* in_sizes, int n_in,
                              void* d_out, int out_size) {
    const float* x      = (const float*)d_in[0];
    const float* W_up   = (const float*)d_in[1];
    const float* conv_w = (const float*)d_in[2];
    const float* conv_b = (const float*)d_in[3];
    const float* Wq     = (const float*)d_in[4];
    const float* Wk     = (const float*)d_in[5];
    const float* Wv     = (const float*)d_in[6];
    const float* ig_w   = (const float*)d_in[7];
    const float* ig_b   = (const float*)d_in[8];
    const float* fg_w   = (const float*)d_in[9];
    const float* fg_b   = (const float*)d_in[10];
    const float* ln_w   = (const float*)d_in[11];
    const float* skip   = (const float*)d_in[12];
    const float* W_down = (const float*)d_in[13];
    float* out = (float*)d_out;

    __half *XS, *UP, *HS, *WTU, *WTD, *GW;
    float *OT;
    cudaGetSymbolAddress((void**)&XS,  g_XS);
    cudaGetSymbolAddress((void**)&UP,  g_UP);
    cudaGetSymbolAddress((void**)&HS,  g_HS);
    cudaGetSymbolAddress((void**)&OT,  g_OT);
    cudaGetSymbolAddress((void**)&WTU, g_WTU);
    cudaGetSymbolAddress((void**)&WTD, g_WTD);
    cudaGetSymbolAddress((void**)&GW,  g_GW);

    cudaFuncSetAttribute(k_seq, cudaFuncAttributeMaxDynamicSharedMemorySize,
                         SM3_FLOATS * (int)sizeof(float));

    k_transpose_in<<<4096, 256>>>(x, XS);
    k_prep<<<408, 256>>>(W_up, W_down, ig_w, fg_w, WTU, WTD, GW);
    // up: UP[131072,512] = XS[131072,128] @ WTU[512,128]^T  (fp16 out)
    k_gemm_h<true><<<dim3(4, 1024), 256>>>(XS, WTU, UP, 512, 128);
    k_seq<<<SEQS, 256, SM3_FLOATS * sizeof(float)>>>(UP, conv_w, conv_b,
        Wq, Wk, Wv, GW, ig_b, fg_b, ln_w, skip, HS);
    // down: OT[131072,128] = HS[131072,256] @ WTD[128,256]^T (fp32 out)
    k_gemm_h<false><<<dim3(1, 1024), 256>>>(HS, WTD, OT, 128, 256);
    k_transpose_out<<<4096, 256>>>(OT, out);
}

// round 11
// speedup vs baseline: 2.0462x; 1.2140x over previous
#include <cuda_runtime.h>
#include <cuda_fp16.h>
#include <cstdint>
#include <math.h>

// ---------------- problem constants ----------------
#define DIMC  128
#define TT    16
#define INNER 256
#define SEQS  8192
#define ROWS  (SEQS*TT)         // 131072
#define UPCOLS 512

// ---------------- scratch (static device, no allocs) ----------------
__device__ __half g_XS[(size_t)ROWS*DIMC];   // [row][128] fp16
__device__ __half g_UP[(size_t)ROWS*UPCOLS]; // [row][512] fp16
__device__ __half g_HS[(size_t)ROWS*INNER];  // [row][256] fp16
__device__ float  g_OT[(size_t)ROWS*DIMC];   // [row][128] fp32
__device__ __half g_WTU[512*128];            // W_up^T  [n][k] fp16
__device__ __half g_WTD[128*256];            // W_down^T [n][k] fp16
__device__ __half g_GW[8*776];               // gate weights g-major [g][776] (j 0..767)

// ---------------- helpers ----------------
__device__ __forceinline__ float siluf(float x){ return x / (1.f + __expf(-x)); }
__device__ __forceinline__ uint32_t smem_u32(const void* p){
    uint32_t a;
    asm("{ .reg .u64 t; cvta.to.shared.u64 t, %1; cvt.u32.u64 %0, t; }" : "=r"(a) : "l"(p));
    return a;
}
__device__ __forceinline__ uint32_t hpack(__half lo, __half hi){
    __half2 h = __halves2half2(lo, hi);
    return *(uint32_t*)&h;
}
__device__ __forceinline__ void mma_16816(float* c, const uint32_t* a, const uint32_t* b){
    asm volatile(
        "mma.sync.aligned.m16n8k16.row.col.f32.f16.f16.f32 "
        "{%0,%1,%2,%3}, {%4,%5,%6,%7}, {%8,%9}, {%0,%1,%2,%3};"
        : "+f"(c[0]), "+f"(c[1]), "+f"(c[2]), "+f"(c[3])
        : "r"(a[0]), "r"(a[1]), "r"(a[2]), "r"(a[3]), "r"(b[0]), "r"(b[1]));
}

// ---------------- kernel: (b,c,t,h,w) -> XS[seq][t][c] (fp16) ----------------
__global__ void __launch_bounds__(256) k_transpose_in(const float* __restrict__ x,
                                                      __half* __restrict__ XS) {
    __shared__ float tile[128*33];
    int bid = blockIdx.x;
    int b = bid >> 9;
    int t = (bid >> 5) & 15;
    int h = bid & 31;
    const float* src = x + ((size_t)(b*128)*16 + t) * 1024 + h*32;
    for (int idx = threadIdx.x; idx < 128*32; idx += 256) {
        int c = idx >> 5, w = idx & 31;
        tile[c*33 + w] = src[(size_t)c*16384 + w];
    }
    __syncthreads();
    size_t base = ((size_t)(b*1024 + h*32) * 16 + t) * 128;
    for (int idx = threadIdx.x; idx < 2048; idx += 256) {
        int w = idx >> 6, c2 = idx & 63;
        __half2 v = __float22half2_rn(make_float2(tile[(2*c2)*33 + w],
                                                  tile[(2*c2+1)*33 + w]));
        *(__half2*)(XS + base + (size_t)w*2048 + 2*c2) = v;
    }
}

// ---------------- kernel: OT[row][c] -> out (b,c,t,h,w) ----------------
__global__ void __launch_bounds__(256) k_transpose_out(const float* __restrict__ OT,
                                                       float* __restrict__ out) {
    __shared__ float tile[128*33];
    int bid = blockIdx.x;
    int b = bid >> 9;
    int t = (bid >> 5) & 15;
    int h = bid & 31;
    size_t base = ((size_t)(b*1024 + h*32) * 16 + t) * 128;
    for (int idx = threadIdx.x; idx < 32*128; idx += 256) {
        int w = idx >> 7, c = idx & 127;
        tile[c*33 + w] = OT[base + (size_t)w*2048 + c];
    }
    __syncthreads();
    float* dst = out + ((size_t)(b*128)*16 + t) * 1024 + h*32;
    for (int idx = threadIdx.x; idx < 128*32; idx += 256) {
        int c = idx >> 5, w = idx & 31;
        dst[(size_t)c*16384 + w] = tile[c*33 + w];
    }
}

// ---------------- merged prep: WTU, WTD, GW (one launch) ----------------
__global__ void k_prep(const float* __restrict__ W_up, const float* __restrict__ W_down,
                       const float* __restrict__ ig_w, const float* __restrict__ fg_w,
                       __half* __restrict__ WTU, __half* __restrict__ WTD,
                       __half* __restrict__ GW){
    int blk = blockIdx.x;
    if (blk < 256) {                                  // WTU: 128x512 -> [512][128]
        int idx = blk*256 + threadIdx.x;
        int k = idx >> 9, n = idx & 511;
        WTU[(size_t)n*128 + k] = __float2half(W_up[idx]);
    } else if (blk < 384) {                           // WTD: 256x128 -> [128][256]
        int idx = (blk-256)*256 + threadIdx.x;
        int k = idx >> 7, n = idx & 127;
        WTD[(size_t)n*256 + k] = __float2half(W_down[idx]);
    } else {                                          // GW pack: g-major [g][776]
        int idx = (blk-384)*256 + threadIdx.x;        // 0..6143
        if (idx < 6144) {
            int j = idx >> 3, g = idx & 7;
            float v = (g < 4) ? ig_w[j*4 + g] : fg_w[j*4 + (g-4)];
            GW[g*776 + j] = __float2half(v);
        }
    }
}

// ---------------- fp16 warp-MMA GEMM: C[M,Ng] = A[M,K] @ Bt[Ng,K]^T ----------------
template<bool HOUT>
__global__ void __launch_bounds__(256) k_gemm_h(const __half* __restrict__ A,
        const __half* __restrict__ Bt, void* __restrict__ Cv, int Ng, int Kf) {
    __shared__ __align__(16) __half As[2][128*40];
    __shared__ __align__(16) __half Bs[2][128*40];
    const int tid  = threadIdx.x;
    const int lane = tid & 31, warp = tid >> 5;
    const int gid  = lane >> 2, tig = lane & 3;
    const int wm0  = (warp >> 1) * 32;
    const int wn0  = (warp & 1) * 64;
    const int m0 = blockIdx.y * 128, n0 = blockIdx.x * 128;
    const int nk = Kf >> 5;

    uint32_t sA0 = smem_u32(As[0]), sA1 = smem_u32(As[1]);
    uint32_t sB0 = smem_u32(Bs[0]), sB1 = smem_u32(Bs[1]);

    float acc[2][8][4];
#pragma unroll
    for (int i = 0; i < 2; i++)
#pragma unroll
        for (int j = 0; j < 8; j++)
#pragma unroll
            for (int e = 0; e < 4; e++) acc[i][j][e] = 0.f;

    auto issue = [&](int kb, int buf){
        uint32_t da_base = buf ? sA1 : sA0;
        uint32_t db_base = buf ? sB1 : sB0;
#pragma unroll
        for (int r = 0; r < 2; r++) {
            int idx = tid + 256*r;
            int row = idx >> 2, c16 = idx & 3;
            const __half* ga = A  + (size_t)(m0+row)*Kf + kb + c16*8;
            const __half* gb = Bt + (size_t)(n0+row)*Kf + kb + c16*8;
            uint32_t da = da_base + row*80 + c16*16;
            uint32_t db = db_base + row*80 + c16*16;
            asm volatile("cp.async.cg.shared.global [%0], [%1], 16;" :: "r"(da), "l"(ga));
            asm volatile("cp.async.cg.shared.global [%0], [%1], 16;" :: "r"(db), "l"(gb));
        }
        asm volatile("cp.async.commit_group;");
    };

    issue(0, 0);
    for (int kc = 0; kc < nk; kc++) {
        if (kc + 1 < nk) {
            issue((kc+1)*32, (kc+1)&1);
            asm volatile("cp.async.wait_group 1;");
        } else {
            asm volatile("cp.async.wait_group 0;");
        }
        __syncthreads();
        const __half2* A2 = (const __half2*)As[kc&1];
        const __half2* B2 = (const __half2*)Bs[kc&1];
#pragma unroll
        for (int ks = 0; ks < 2; ks++) {
            const int k2b = ks*8;
            uint32_t a[2][4], b[8][2];
#pragma unroll
            for (int i = 0; i < 2; i++) {
                int r = wm0 + i*16 + gid;
                a[i][0] = *(const uint32_t*)&A2[r*20 + k2b + tig];
                a[i][1] = *(const uint32_t*)&A2[(r+8)*20 + k2b + tig];
                a[i][2] = *(const uint32_t*)&A2[r*20 + k2b + tig + 4];
                a[i][3] = *(const uint32_t*)&A2[(r+8)*20 + k2b + tig + 4];
            }
#pragma unroll
            for (int j = 0; j < 8; j++) {
                int rn = wn0 + j*8 + gid;
                b[j][0] = *(const uint32_t*)&B2[rn*20 + k2b + tig];
                b[j][1] = *(const uint32_t*)&B2[rn*20 + k2b + tig + 4];
            }
#pragma unroll
            for (int i = 0; i < 2; i++)
#pragma unroll
                for (int j = 0; j < 8; j++)
                    mma_16816(acc[i][j], a[i], b[j]);
        }
        __syncthreads();
    }
#pragma unroll
    for (int i = 0; i < 2; i++) {
        int row = m0 + wm0 + i*16 + gid;
#pragma unroll
        for (int j = 0; j < 8; j++) {
            int col = n0 + wn0 + j*8 + tig*2;
            if (HOUT) {
                __half* C = (__half*)Cv;
                *(__half2*)(C + (size_t)row*Ng + col) =
                    __float22half2_rn(make_float2(acc[i][j][0], acc[i][j][1]));
                *(__half2*)(C + (size_t)(row+8)*Ng + col) =
                    __float22half2_rn(make_float2(acc[i][j][2], acc[i][j][3]));
            } else {
                float* C = (float*)Cv;
                *(float2*)(C + (size_t)row*Ng + col)     = make_float2(acc[i][j][0], acc[i][j][1]);
                *(float2*)(C + (size_t)(row+8)*Ng + col) = make_float2(acc[i][j][2], acc[i][j][3]);
            }
        }
    }
}

// ---------------- per-sequence fused middle ----------------
// float map + half map. HT aliases dead XM.
#define S_XM   0        // [16][256] fp32 x_m ; later HT [i][s] stride 17 (4352 f)
#define S_HT   0
// half arrays (indices in __half units); Q/K/XC row stride 264
#define H_XC   8704     // xc  [t][264]  (4224 h)
#define H_Q    12928    // q   [t][264]  (4224 h)
#define H_K    17152    // k   [t][264]  (4224 h)
#define H_V    21376    // v   [i][18]   (4608 h)
#define H_GW   25984    // gate weights g-major [8][776] (6208 h)
#define H_WM   32192    // wm  [h][s][t] (1024 h) ends 33216
// float arrays resume: 33216/2 = 16608
#define S_GP   16608    // 1024 f scratch: gate partials [w][t][g] / qk fp32 [h][s][t]
#define S_IG   17632    // [t][4]
#define S_FG   17696    // [t][4]
#define S_LFC  17760    // [h][17]
#define S_AA   17828    // [h][16]
#define SM3_FLOATS 17892   // 71.6 KB

__global__ void __launch_bounds__(256,3) k_seq(
    const __half* __restrict__ UP,
    const float* __restrict__ conv_w, const float* __restrict__ conv_b,
    const float* __restrict__ Wq, const float* __restrict__ Wk, const float* __restrict__ Wv,
    const __half* __restrict__ GW,
    const float* __restrict__ ig_b, const float* __restrict__ fg_b,
    const float* __restrict__ ln_w, const float* __restrict__ skip,
    __half* __restrict__ HS) {
    extern __shared__ float sm[];
    __half* smh = (__half*)sm;
    const int tid = threadIdx.x;
    const int seq = blockIdx.x;
    const int warp = tid >> 5, lane = tid & 31;
    const int gid = lane >> 2, tig = lane & 3;

    // --- A: load x_m [16][256] (fp16 -> fp32 smem) + gate weights ---
    {
        const uint4* src = (const uint4*)(UP + (size_t)seq * 16 * 512);
#pragma unroll
        for (int rr = 0; rr < 2; rr++) {
            int i = tid + 256*rr;
            int row = i >> 5, q = i & 31;
            uint4 v = src[row*64 + q];
            const __half2* hp = (const __half2*)&v;
            float2 f0 = __half22float2(hp[0]);
            float2 f1 = __half22float2(hp[1]);
            float2 f2 = __half22float2(hp[2]);
            float2 f3 = __half22float2(hp[3]);
            float* dst = &sm[S_XM + row*256 + q*8];
            *(float4*)dst     = make_float4(f0.x, f0.y, f1.x, f1.y);
            *(float4*)(dst+4) = make_float4(f2.x, f2.y, f3.x, f3.y);
        }
        const uint4* gsrc = (const uint4*)GW;
        uint4* gdst = (uint4*)&smh[H_GW];
        for (int r = tid; r < 776; r += 256) gdst[r] = gsrc[r];
    }
    __syncthreads();

    // --- BC: fused conv+silu -> xc, then block-diagonal q,k,v ---
    {
        const int n = tid & 63;
        const int t0 = tid >> 6;
        float4 cw[4];
#pragma unroll
        for (int j = 0; j < 4; j++) cw[j] = *(const float4*)(conv_w + j*256 + n*4);
        const float4 cb = *(const float4*)(conv_b + n*4);
#pragma unroll
        for (int r = 0; r < 4; r++) {
            int t = t0 + r*4;
            float4 a4 = cb;
#pragma unroll
            for (int j = 0; j < 4; j++) {
                int tt = t + j - 3;
                if (tt >= 0) {
                    float4 xm = *(const float4*)&sm[S_XM + tt*256 + n*4];
                    a4.x += cw[j].x*xm.x; a4.y += cw[j].y*xm.y;
                    a4.z += cw[j].z*xm.z; a4.w += cw[j].w*xm.w;
                }
            }
            float4 xm_t = *(const float4*)&sm[S_XM + t*256 + n*4];
            float4 xc;
            xc.x = siluf(a4.x); xc.y = siluf(a4.y);
            xc.z = siluf(a4.z); xc.w = siluf(a4.w);
            *(__half2*)&smh[H_XC + t*264 + n*4]     = __float22half2_rn(make_float2(xc.x, xc.y));
            *(__half2*)&smh[H_XC + t*264 + n*4 + 2] = __float22half2_rn(make_float2(xc.z, xc.w));
            float qv[4], kv[4], vv[4];
#pragma unroll
            for (int o = 0; o < 4; o++) {
                float4 wq = *(const float4*)(Wq + n*16 + o*4);
                float4 wk = *(const float4*)(Wk + n*16 + o*4);
                float4 wv = *(const float4*)(Wv + n*16 + o*4);
                qv[o] = xc.x*wq.x + xc.y*wq.y + xc.z*wq.z + xc.w*wq.w;
                kv[o] = xc.x*wk.x + xc.y*wk.y + xc.z*wk.z + xc.w*wk.w;
                vv[o] = xm_t.x*wv.x + xm_t.y*wv.y + xm_t.z*wv.z + xm_t.w*wv.w;
            }
            *(__half2*)&smh[H_Q + t*264 + n*4]     = __float22half2_rn(make_float2(qv[0], qv[1]));
            *(__half2*)&smh[H_Q + t*264 + n*4 + 2] = __float22half2_rn(make_float2(qv[2], qv[3]));
            *(__half2*)&smh[H_K + t*264 + n*4]     = __float22half2_rn(make_float2(kv[0], kv[1]));
            *(__half2*)&smh[H_K + t*264 + n*4 + 2] = __float22half2_rn(make_float2(kv[2], kv[3]));
#pragma unroll
            for (int o = 0; o < 4; o++)
                smh[H_V + (n*4+o)*18 + t] = __float2half(vv[o]);
        }
    }
    __syncthreads();

    // --- D: gates via MMA. if_in[16 x 768] @ GW^T[768 x 8]; warp w owns j in [w*96, w*96+96) ---
    {
        float c[4] = {0.f, 0.f, 0.f, 0.f};
#pragma unroll
        for (int ck = 0; ck < 6; ck++) {
            int jb = warp*96 + ck*16;
            uint32_t a[4], b[2];
            if (jb < 256) {
                int base = H_Q + jb + tig*2;
                a[0] = *(const uint32_t*)&smh[base + gid*264];
                a[1] = *(const uint32_t*)&smh[base + (gid+8)*264];
                a[2] = *(const uint32_t*)&smh[base + gid*264 + 8];
                a[3] = *(const uint32_t*)&smh[base + (gid+8)*264 + 8];
            } else if (jb < 512) {
                int base = H_K + (jb - 256) + tig*2;
                a[0] = *(const uint32_t*)&smh[base + gid*264];
                a[1] = *(const uint32_t*)&smh[base + (gid+8)*264];
                a[2] = *(const uint32_t*)&smh[base + gid*264 + 8];
                a[3] = *(const uint32_t*)&smh[base + (gid+8)*264 + 8];
            } else {
                int jo = jb - 512 + tig*2;
                a[0] = hpack(smh[H_V + jo*18 + gid],       smh[H_V + (jo+1)*18 + gid]);
                a[1] = hpack(smh[H_V + jo*18 + gid + 8],   smh[H_V + (jo+1)*18 + gid + 8]);
                a[2] = hpack(smh[H_V + (jo+8)*18 + gid],   smh[H_V + (jo+9)*18 + gid]);
                a[3] = hpack(smh[H_V + (jo+8)*18 + gid+8], smh[H_V + (jo+9)*18 + gid + 8]);
            }
            b[0] = *(const uint32_t*)&smh[H_GW + gid*776 + jb + tig*2];
            b[1] = *(const uint32_t*)&smh[H_GW + gid*776 + jb + tig*2 + 8];
            mma_16816(c, a, b);
        }
        *(float2*)&sm[S_GP + warp*128 + gid*8 + tig*2]     = make_float2(c[0], c[1]);
        *(float2*)&sm[S_GP + warp*128 + (gid+8)*8 + tig*2] = make_float2(c[2], c[3]);
    }
    __syncthreads();

    // --- D2: reduce 8 warp partials -> ig/fg preacts ---
    if (tid < 128) {
        int t = tid >> 3, g = tid & 7;
        float s2 = 0.f;
#pragma unroll
        for (int w = 0; w < 8; w++) s2 += sm[S_GP + w*128 + tid];
        if (g < 4) sm[S_IG + t*4 + g]       = s2 + ig_b[g];
        else       sm[S_FG + t*4 + (g-4)]   = s2 + fg_b[g-4];
    }
    __syncthreads();

    // --- E: prefix scan of log-sigmoid(fg) (warps 0-1) ---
    if (tid < 64) {
        int h = tid >> 4, t = tid & 15;
        float fgv = sm[S_FG + t*4 + h];
        float cum = fminf(fgv, 0.f) - __logf(1.f + __expf(-fabsf(fgv)));
#pragma unroll
        for (int m = 1; m < 16; m <<= 1) {
            float o = __shfl_up_sync(0xffffffffu, cum, m, 16);
            if ((tid & 15) >= m) cum += o;
        }
        sm[S_LFC + h*17 + t + 1] = cum;
        if (t == 0) sm[S_LFC + h*17] = 0.f;
        sm[S_AA + h*16 + t] = sm[S_IG + t*4 + h] - cum;
    }

    // --- F1: qk via MMA. Per head Q[16x64] @ K^T -> qk fp32 in S_GP[h][s][t] ---
    {
        const int h = warp >> 1, nc = warp & 1;
        const int hd = h*64;
        float c[4] = {0.f, 0.f, 0.f, 0.f};
#pragma unroll
        for (int kc = 0; kc < 4; kc++) {
            int d0 = hd + kc*16 + tig*2;
            uint32_t a[4], b[2];
            a[0] = *(const uint32_t*)&smh[H_Q + gid*264 + d0];
            a[1] = *(const uint32_t*)&smh[H_Q + (gid+8)*264 + d0];
            a[2] = *(const uint32_t*)&smh[H_Q + gid*264 + d0 + 8];
            a[3] = *(const uint32_t*)&smh[H_Q + (gid+8)*264 + d0 + 8];
            b[0] = *(const uint32_t*)&smh[H_K + (nc*8+gid)*264 + d0];
            b[1] = *(const uint32_t*)&smh[H_K + (nc*8+gid)*264 + d0 + 8];
            mma_16816(c, a, b);
        }
        *(float2*)&sm[S_GP + h*256 + gid*16 + nc*8 + tig*2]     = make_float2(c[0], c[1]);
        *(float2*)&sm[S_GP + h*256 + (gid+8)*16 + nc*8 + tig*2] = make_float2(c[2], c[3]);
    }
    __syncthreads();

    // --- F2: D-weights + normalizer -> wm (fp16) ---
    const int mh = tid >> 6;
    const int ms = (tid >> 2) & 15;
    const int mtq = tid & 3;
    {
        float4 q4 = *(const float4*)&sm[S_GP + mh*256 + ms*16 + mtq*4];
        float qkv4[4] = {q4.x, q4.y, q4.z, q4.w};
        float cs = sm[S_LFC + mh*17 + ms + 1];
        float mloc = -1e30f;
        float ldv[4];
#pragma unroll
        for (int j = 0; j < 4; j++) {
            int t = mtq*4 + j;
            if (t <= ms) { ldv[j] = cs + sm[S_AA + mh*16 + t]; mloc = fmaxf(mloc, ldv[j]); }
            else ldv[j] = 0.f;
        }
        mloc = fmaxf(mloc, __shfl_xor_sync(0xffffffffu, mloc, 1));
        mloc = fmaxf(mloc, __shfl_xor_sync(0xffffffffu, mloc, 2));
        float cv[4]; float csum = 0.f;
#pragma unroll
        for (int j = 0; j < 4; j++) {
            int t = mtq*4 + j;
            cv[j] = (t <= ms) ? (qkv4[j]*0.125f) * __expf(ldv[j] - mloc) : 0.f;
            csum += cv[j];
        }
        csum += __shfl_xor_sync(0xffffffffu, csum, 1);
        csum += __shfl_xor_sync(0xffffffffu, csum, 2);
        float norm = fmaxf(fabsf(csum), __expf(-mloc)) + 1e-6f;
        float inv = 1.f / norm;
        int wb = H_WM + (mh*16 + ms)*16 + mtq*4;
        *(__half2*)&smh[wb]     = __float22half2_rn(make_float2(cv[0]*inv, cv[1]*inv));
        *(__half2*)&smh[wb + 2] = __float22half2_rn(make_float2(cv[2]*inv, cv[3]*inv));
    }
    __syncthreads();

    // --- G: out = wm @ v via MMA -> HT (aliases dead XM) ---
    {
        const int h = warp >> 1;
        uint32_t a[4];
        int ab = H_WM + h*256 + gid*16 + tig*2;
        a[0] = *(const uint32_t*)&smh[ab];
        a[1] = *(const uint32_t*)&smh[ab + 128];
        a[2] = *(const uint32_t*)&smh[ab + 8];
        a[3] = *(const uint32_t*)&smh[ab + 136];
#pragma unroll
        for (int dc = 0; dc < 4; dc++) {
            int dbase = ((warp & 1)*4 + dc)*8;
            uint32_t b[2];
            int vb = H_V + (h*64 + dbase + gid)*18 + tig*2;
            b[0] = *(const uint32_t*)&smh[vb];
            b[1] = *(const uint32_t*)&smh[vb + 8];
            float c[4] = {0.f, 0.f, 0.f, 0.f};
            mma_16816(c, a, b);
            int i0 = h*64 + dbase + tig*2;
            sm[S_HT + i0*17 + gid]         = c[0];
            sm[S_HT + (i0+1)*17 + gid]     = c[1];
            sm[S_HT + i0*17 + gid + 8]     = c[2];
            sm[S_HT + (i0+1)*17 + gid + 8] = c[3];
        }
    }
    __syncthreads();

    // --- H: group LayerNorm + skip*xc + silu(z) gate ---
    {
        int hD = tid >> 6, sD = (tid >> 2) & 15, dq = tid & 3;
        float vals[16]; float sum = 0.f, sq = 0.f;
#pragma unroll
        for (int dd = 0; dd < 16; dd++) {
            int i = hD*64 + dq*16 + dd;
            float v = sm[S_HT + i*17 + sD];
            vals[dd] = v; sum += v; sq += v*v;
        }
        sum += __shfl_xor_sync(0xffffffffu, sum, 1);
        sum += __shfl_xor_sync(0xffffffffu, sum, 2);
        sq  += __shfl_xor_sync(0xffffffffu, sq, 1);
        sq  += __shfl_xor_sync(0xffffffffu, sq, 2);
        float mu = sum * (1.f/64.f);
        float var = sq * (1.f/64.f) - mu*mu;
        float rstd = rsqrtf(var + 1e-5f);
        int ib0 = hD*64 + dq*16;
        const __half* zrow = UP + (size_t)seq*8192 + sD*512 + 256 + ib0;
        uint4 zr0 = *(const uint4*)zrow;
        uint4 zr1 = *(const uint4*)(zrow + 8);
        float zz[16];
        {
            const __half2* z2 = (const __half2*)&zr0;
#pragma unroll
            for (int u = 0; u < 4; u++) {
                float2 f = __half22float2(z2[u]);
                zz[2*u] = f.x; zz[2*u+1] = f.y;
            }
            const __half2* z3 = (const __half2*)&zr1;
#pragma unroll
            for (int u = 0; u < 4; u++) {
                float2 f = __half22float2(z3[u]);
                zz[8+2*u] = f.x; zz[8+2*u+1] = f.y;
            }
        }
#pragma unroll
        for (int dd = 0; dd < 16; dd++) {
            int i = ib0 + dd;
            float hn = (vals[dd] - mu) * rstd * ln_w[i];
            float xcv = __half2float(smh[H_XC + sD*264 + i]);
            float o = (hn + skip[i] * xcv) * siluf(zz[dd]);
            sm[S_HT + i*17 + sD] = o;
        }
    }
    __syncthreads();

    // --- coalesced write HS[row][i] (fp16) ---
    {
        __half2* dst = (__half2*)(HS + (size_t)seq * 16 * 256);
        for (int idx = tid; idx < 2048; idx += 256) {
            int t = idx >> 7, i2 = idx & 127;
            float v0 = sm[S_HT + (2*i2)*17 + t];
            float v1 = sm[S_HT + (2*i2+1)*17 + t];
            dst[idx] = __float22half2_rn(make_float2(v0, v1));
        }
    }
}

// ---------------- launch ----------------
extern "C" void kernel_launch(void* const* d_in, const int* in_sizes, int n_in,
                              void* d_out, int out_size) {
    const float* x      = (const float*)d_in[0];
    const float* W_up   = (const float*)d_in[1];
    const float* conv_w = (const float*)d_in[2];
    const float* conv_b = (const float*)d_in[3];
    const float* Wq     = (const float*)d_in[4];
    const float* Wk     = (const float*)d_in[5];
    const float* Wv     = (const float*)d_in[6];
    const float* ig_w   = (const float*)d_in[7];
    const float* ig_b   = (const float*)d_in[8];
    const float* fg_w   = (const float*)d_in[9];
    const float* fg_b   = (const float*)d_in[10];
    const float* ln_w   = (const float*)d_in[11];
    const float* skip   = (const float*)d_in[12];
    const float* W_down = (const float*)d_in[13];
    float* out = (float*)d_out;

    __half *XS, *UP, *HS, *WTU, *WTD, *GW;
    float *OT;
    cudaGetSymbolAddress((void**)&XS,  g_XS);
    cudaGetSymbolAddress((void**)&UP,  g_UP);
    cudaGetSymbolAddress((void**)&HS,  g_HS);
    cudaGetSymbolAddress((void**)&OT,  g_OT);
    cudaGetSymbolAddress((void**)&WTU, g_WTU);
    cudaGetSymbolAddress((void**)&WTD, g_WTD);
    cudaGetSymbolAddress((void**)&GW,  g_GW);

    cudaFuncSetAttribute(k_seq, cudaFuncAttributeMaxDynamicSharedMemorySize,
                         SM3_FLOATS * (int)sizeof(float));

    k_transpose_in<<<4096, 256>>>(x, XS);
    k_prep<<<408, 256>>>(W_up, W_down, ig_w, fg_w, WTU, WTD, GW);
    // up: UP[131072,512] = XS[131072,128] @ WTU[512,128]^T  (fp16 out)
    k_gemm_h<true><<<dim3(4, 1024), 256>>>(XS, WTU, UP, 512, 128);
    k_seq<<<SEQS, 256, SM3_FLOATS * sizeof(float)>>>(UP, conv_w, conv_b,
        Wq, Wk, Wv, GW, ig_b, fg_b, ln_w, skip, HS);
    // down: OT[131072,128] = HS[131072,256] @ WTD[128,256]^T (fp32 out)
    k_gemm_h<false><<<dim3(1, 1024), 256>>>(HS, WTD, OT, 128, 256);
    k_transpose_out<<<4096, 256>>>(OT, out);
}

// round 12
// speedup vs baseline: 2.1746x; 1.0627x over previous
#include <cuda_runtime.h>
#include <cuda_fp16.h>
#include <cstdint>
#include <math.h>

// ---------------- problem constants ----------------
#define DIMC  128
#define TT    16
#define INNER 256
#define SEQS  8192
#define ROWS  (SEQS*TT)         // 131072
#define UPCOLS 512

// ---------------- scratch (static device, no allocs) ----------------
__device__ __half g_XS[(size_t)ROWS*DIMC];   // [row][128] fp16
__device__ __half g_UP[(size_t)ROWS*UPCOLS]; // [row][512] fp16
__device__ __half g_HS[(size_t)ROWS*INNER];  // [row][256] fp16
__device__ float  g_OT[(size_t)ROWS*DIMC];   // [row][128] fp32
__device__ __half g_WTU[512*128];            // W_up^T  [n][k] fp16
__device__ __half g_WTD[128*256];            // W_down^T [n][k] fp16
__device__ __half g_GW[8*776];               // gate weights g-major [g][776]

// ---------------- helpers ----------------
__device__ __forceinline__ float siluf(float x){ return x / (1.f + __expf(-x)); }
__device__ __forceinline__ uint32_t smem_u32(const void* p){
    uint32_t a;
    asm("{ .reg .u64 t; cvta.to.shared.u64 t, %1; cvt.u32.u64 %0, t; }" : "=r"(a) : "l"(p));
    return a;
}
__device__ __forceinline__ uint32_t hpack(__half lo, __half hi){
    __half2 h = __halves2half2(lo, hi);
    return *(uint32_t*)&h;
}
__device__ __forceinline__ void mma_16816(float* c, const uint32_t* a, const uint32_t* b){
    asm volatile(
        "mma.sync.aligned.m16n8k16.row.col.f32.f16.f16.f32 "
        "{%0,%1,%2,%3}, {%4,%5,%6,%7}, {%8,%9}, {%0,%1,%2,%3};"
        : "+f"(c[0]), "+f"(c[1]), "+f"(c[2]), "+f"(c[3])
        : "r"(a[0]), "r"(a[1]), "r"(a[2]), "r"(a[3]), "r"(b[0]), "r"(b[1]));
}
__device__ __forceinline__ void unpack8(uint4 v, float* f){
    const __half2* hp = (const __half2*)&v;
#pragma unroll
    for (int u = 0; u < 4; u++) {
        float2 t = __half22float2(hp[u]);
        f[2*u] = t.x; f[2*u+1] = t.y;
    }
}

// ---------------- kernel: (b,c,t,h,w) -> XS[seq][t][c] (fp16) ----------------
__global__ void __launch_bounds__(256) k_transpose_in(const float* __restrict__ x,
                                                      __half* __restrict__ XS) {
    __shared__ float tile[128*33];
    int bid = blockIdx.x;
    int b = bid >> 9;
    int t = (bid >> 5) & 15;
    int h = bid & 31;
    const float* src = x + ((size_t)(b*128)*16 + t) * 1024 + h*32;
    for (int idx = threadIdx.x; idx < 128*32; idx += 256) {
        int c = idx >> 5, w = idx & 31;
        tile[c*33 + w] = src[(size_t)c*16384 + w];
    }
    __syncthreads();
    size_t base = ((size_t)(b*1024 + h*32) * 16 + t) * 128;
    for (int idx = threadIdx.x; idx < 2048; idx += 256) {
        int w = idx >> 6, c2 = idx & 63;
        __half2 v = __float22half2_rn(make_float2(tile[(2*c2)*33 + w],
                                                  tile[(2*c2+1)*33 + w]));
        *(__half2*)(XS + base + (size_t)w*2048 + 2*c2) = v;
    }
}

// ---------------- kernel: OT[row][c] -> out (b,c,t,h,w) ----------------
__global__ void __launch_bounds__(256) k_transpose_out(const float* __restrict__ OT,
                                                       float* __restrict__ out) {
    __shared__ float tile[128*33];
    int bid = blockIdx.x;
    int b = bid >> 9;
    int t = (bid >> 5) & 15;
    int h = bid & 31;
    size_t base = ((size_t)(b*1024 + h*32) * 16 + t) * 128;
    for (int idx = threadIdx.x; idx < 32*128; idx += 256) {
        int w = idx >> 7, c = idx & 127;
        tile[c*33 + w] = OT[base + (size_t)w*2048 + c];
    }
    __syncthreads();
    float* dst = out + ((size_t)(b*128)*16 + t) * 1024 + h*32;
    for (int idx = threadIdx.x; idx < 128*32; idx += 256) {
        int c = idx >> 5, w = idx & 31;
        dst[(size_t)c*16384 + w] = tile[c*33 + w];
    }
}

// ---------------- merged prep: WTU, WTD, GW (one launch) ----------------
__global__ void k_prep(const float* __restrict__ W_up, const float* __restrict__ W_down,
                       const float* __restrict__ ig_w, const float* __restrict__ fg_w,
                       __half* __restrict__ WTU, __half* __restrict__ WTD,
                       __half* __restrict__ GW){
    int blk = blockIdx.x;
    if (blk < 256) {
        int idx = blk*256 + threadIdx.x;
        int k = idx >> 9, n = idx & 511;
        WTU[(size_t)n*128 + k] = __float2half(W_up[idx]);
    } else if (blk < 384) {
        int idx = (blk-256)*256 + threadIdx.x;
        int k = idx >> 7, n = idx & 127;
        WTD[(size_t)n*256 + k] = __float2half(W_down[idx]);
    } else {
        int idx = (blk-384)*256 + threadIdx.x;
        if (idx < 6144) {
            int j = idx >> 3, g = idx & 7;
            float v = (g < 4) ? ig_w[j*4 + g] : fg_w[j*4 + (g-4)];
            GW[g*776 + j] = __float2half(v);
        }
    }
}

// ---------------- fp16 warp-MMA GEMM: C[M,Ng] = A[M,K] @ Bt[Ng,K]^T ----------------
template<bool HOUT>
__global__ void __launch_bounds__(256) k_gemm_h(const __half* __restrict__ A,
        const __half* __restrict__ Bt, void* __restrict__ Cv, int Ng, int Kf) {
    __shared__ __align__(16) __half As[2][128*40];
    __shared__ __align__(16) __half Bs[2][128*40];
    const int tid  = threadIdx.x;
    const int lane = tid & 31, warp = tid >> 5;
    const int gid  = lane >> 2, tig = lane & 3;
    const int wm0  = (warp >> 1) * 32;
    const int wn0  = (warp & 1) * 64;
    const int m0 = blockIdx.y * 128, n0 = blockIdx.x * 128;
    const int nk = Kf >> 5;

    uint32_t sA0 = smem_u32(As[0]), sA1 = smem_u32(As[1]);
    uint32_t sB0 = smem_u32(Bs[0]), sB1 = smem_u32(Bs[1]);

    float acc[2][8][4];
#pragma unroll
    for (int i = 0; i < 2; i++)
#pragma unroll
        for (int j = 0; j < 8; j++)
#pragma unroll
            for (int e = 0; e < 4; e++) acc[i][j][e] = 0.f;

    auto issue = [&](int kb, int buf){
        uint32_t da_base = buf ? sA1 : sA0;
        uint32_t db_base = buf ? sB1 : sB0;
#pragma unroll
        for (int r = 0; r < 2; r++) {
            int idx = tid + 256*r;
            int row = idx >> 2, c16 = idx & 3;
            const __half* ga = A  + (size_t)(m0+row)*Kf + kb + c16*8;
            const __half* gb = Bt + (size_t)(n0+row)*Kf + kb + c16*8;
            uint32_t da = da_base + row*80 + c16*16;
            uint32_t db = db_base + row*80 + c16*16;
            asm volatile("cp.async.cg.shared.global [%0], [%1], 16;" :: "r"(da), "l"(ga));
            asm volatile("cp.async.cg.shared.global [%0], [%1], 16;" :: "r"(db), "l"(gb));
        }
        asm volatile("cp.async.commit_group;");
    };

    issue(0, 0);
    for (int kc = 0; kc < nk; kc++) {
        if (kc + 1 < nk) {
            issue((kc+1)*32, (kc+1)&1);
            asm volatile("cp.async.wait_group 1;");
        } else {
            asm volatile("cp.async.wait_group 0;");
        }
        __syncthreads();
        const __half2* A2 = (const __half2*)As[kc&1];
        const __half2* B2 = (const __half2*)Bs[kc&1];
#pragma unroll
        for (int ks = 0; ks < 2; ks++) {
            const int k2b = ks*8;
            uint32_t a[2][4], b[8][2];
#pragma unroll
            for (int i = 0; i < 2; i++) {
                int r = wm0 + i*16 + gid;
                a[i][0] = *(const uint32_t*)&A2[r*20 + k2b + tig];
                a[i][1] = *(const uint32_t*)&A2[(r+8)*20 + k2b + tig];
                a[i][2] = *(const uint32_t*)&A2[r*20 + k2b + tig + 4];
                a[i][3] = *(const uint32_t*)&A2[(r+8)*20 + k2b + tig + 4];
            }
#pragma unroll
            for (int j = 0; j < 8; j++) {
                int rn = wn0 + j*8 + gid;
                b[j][0] = *(const uint32_t*)&B2[rn*20 + k2b + tig];
                b[j][1] = *(const uint32_t*)&B2[rn*20 + k2b + tig + 4];
            }
#pragma unroll
            for (int i = 0; i < 2; i++)
#pragma unroll
                for (int j = 0; j < 8; j++)
                    mma_16816(acc[i][j], a[i], b[j]);
        }
        __syncthreads();
    }
#pragma unroll
    for (int i = 0; i < 2; i++) {
        int row = m0 + wm0 + i*16 + gid;
#pragma unroll
        for (int j = 0; j < 8; j++) {
            int col = n0 + wn0 + j*8 + tig*2;
            if (HOUT) {
                __half* C = (__half*)Cv;
                *(__half2*)(C + (size_t)row*Ng + col) =
                    __float22half2_rn(make_float2(acc[i][j][0], acc[i][j][1]));
                *(__half2*)(C + (size_t)(row+8)*Ng + col) =
                    __float22half2_rn(make_float2(acc[i][j][2], acc[i][j][3]));
            } else {
                float* C = (float*)Cv;
                *(float2*)(C + (size_t)row*Ng + col)     = make_float2(acc[i][j][0], acc[i][j][1]);
                *(float2*)(C + (size_t)(row+8)*Ng + col) = make_float2(acc[i][j][2], acc[i][j][3]);
            }
        }
    }
}

// ---------------- per-sequence fused middle ----------------
// float map + half map. HT (fp16 [s][264]) aliases dead XM region.
#define S_XM   0        // [16][256] fp32 x_m (phase A/BC only)
#define H_HT   0        // ht  [s][264] fp16 (phase G/H; aliases XM)
// half arrays (indices in __half units); row stride 264
#define H_XC   8704     // xc  [t][264]  (4224 h)
#define H_Q    12928    // q   [t][264]  (4224 h)
#define H_K    17152    // k   [t][264]  (4224 h)
#define H_V    21376    // v   [i][18]   (4608 h)
#define H_GW   25984    // gate weights g-major [8][776] (6208 h)
#define H_WM   32192    // wm  [h][s][t] (1024 h) ends 33216
// float arrays resume: 33216/2 = 16608
#define S_GP   16608    // 1024 f scratch: gate partials / qk fp32
#define S_IG   17632    // [t][4]
#define S_FG   17696    // [t][4]
#define S_LFC  17760    // [h][17]
#define S_AA   17828    // [h][16]
#define SM3_FLOATS 17892   // 71.6 KB

__global__ void __launch_bounds__(256,3) k_seq(
    const __half* __restrict__ UP,
    const float* __restrict__ conv_w, const float* __restrict__ conv_b,
    const float* __restrict__ Wq, const float* __restrict__ Wk, const float* __restrict__ Wv,
    const __half* __restrict__ GW,
    const float* __restrict__ ig_b, const float* __restrict__ fg_b,
    const float* __restrict__ ln_w, const float* __restrict__ skip,
    __half* __restrict__ HS) {
    extern __shared__ float sm[];
    __half* smh = (__half*)sm;
    const int tid = threadIdx.x;
    const int seq = blockIdx.x;
    const int warp = tid >> 5, lane = tid & 31;
    const int gid = lane >> 2, tig = lane & 3;

    // --- A: load x_m [16][256] (fp16 -> fp32 smem) + gate weights ---
    {
        const uint4* src = (const uint4*)(UP + (size_t)seq * 16 * 512);
#pragma unroll
        for (int rr = 0; rr < 2; rr++) {
            int i = tid + 256*rr;
            int row = i >> 5, q = i & 31;
            uint4 v = src[row*64 + q];
            float f[8];
            unpack8(v, f);
            float* dst = &sm[S_XM + row*256 + q*8];
            *(float4*)dst     = make_float4(f[0], f[1], f[2], f[3]);
            *(float4*)(dst+4) = make_float4(f[4], f[5], f[6], f[7]);
        }
        const uint4* gsrc = (const uint4*)GW;
        uint4* gdst = (uint4*)&smh[H_GW];
        for (int r = tid; r < 776; r += 256) gdst[r] = gsrc[r];
    }
    __syncthreads();

    // --- BC: fused conv+silu -> xc, then block-diagonal q,k,v ---
    {
        const int n = tid & 63;
        const int t0 = tid >> 6;
        float4 cw[4];
#pragma unroll
        for (int j = 0; j < 4; j++) cw[j] = *(const float4*)(conv_w + j*256 + n*4);
        const float4 cb = *(const float4*)(conv_b + n*4);
#pragma unroll
        for (int r = 0; r < 4; r++) {
            int t = t0 + r*4;
            float4 a4 = cb;
#pragma unroll
            for (int j = 0; j < 4; j++) {
                int tt = t + j - 3;
                if (tt >= 0) {
                    float4 xm = *(const float4*)&sm[S_XM + tt*256 + n*4];
                    a4.x += cw[j].x*xm.x; a4.y += cw[j].y*xm.y;
                    a4.z += cw[j].z*xm.z; a4.w += cw[j].w*xm.w;
                }
            }
            float4 xm_t = *(const float4*)&sm[S_XM + t*256 + n*4];
            float4 xc;
            xc.x = siluf(a4.x); xc.y = siluf(a4.y);
            xc.z = siluf(a4.z); xc.w = siluf(a4.w);
            *(__half2*)&smh[H_XC + t*264 + n*4]     = __float22half2_rn(make_float2(xc.x, xc.y));
            *(__half2*)&smh[H_XC + t*264 + n*4 + 2] = __float22half2_rn(make_float2(xc.z, xc.w));
            float qv[4], kv[4], vv[4];
#pragma unroll
            for (int o = 0; o < 4; o++) {
                float4 wq = *(const float4*)(Wq + n*16 + o*4);
                float4 wk = *(const float4*)(Wk + n*16 + o*4);
                float4 wv = *(const float4*)(Wv + n*16 + o*4);
                qv[o] = xc.x*wq.x + xc.y*wq.y + xc.z*wq.z + xc.w*wq.w;
                kv[o] = xc.x*wk.x + xc.y*wk.y + xc.z*wk.z + xc.w*wk.w;
                vv[o] = xm_t.x*wv.x + xm_t.y*wv.y + xm_t.z*wv.z + xm_t.w*wv.w;
            }
            *(__half2*)&smh[H_Q + t*264 + n*4]     = __float22half2_rn(make_float2(qv[0], qv[1]));
            *(__half2*)&smh[H_Q + t*264 + n*4 + 2] = __float22half2_rn(make_float2(qv[2], qv[3]));
            *(__half2*)&smh[H_K + t*264 + n*4]     = __float22half2_rn(make_float2(kv[0], kv[1]));
            *(__half2*)&smh[H_K + t*264 + n*4 + 2] = __float22half2_rn(make_float2(kv[2], kv[3]));
#pragma unroll
            for (int o = 0; o < 4; o++)
                smh[H_V + (n*4+o)*18 + t] = __float2half(vv[o]);
        }
    }
    __syncthreads();

    // --- D: gates via MMA. if_in[16 x 768] @ GW^T[768 x 8]; warp w owns j in [w*96, (w+1)*96) ---
    {
        float c[4] = {0.f, 0.f, 0.f, 0.f};
#pragma unroll
        for (int ck = 0; ck < 6; ck++) {
            int jb = warp*96 + ck*16;
            uint32_t a[4], b[2];
            if (jb < 256) {
                int base = H_Q + jb + tig*2;
                a[0] = *(const uint32_t*)&smh[base + gid*264];
                a[1] = *(const uint32_t*)&smh[base + (gid+8)*264];
                a[2] = *(const uint32_t*)&smh[base + gid*264 + 8];
                a[3] = *(const uint32_t*)&smh[base + (gid+8)*264 + 8];
            } else if (jb < 512) {
                int base = H_K + (jb - 256) + tig*2;
                a[0] = *(const uint32_t*)&smh[base + gid*264];
                a[1] = *(const uint32_t*)&smh[base + (gid+8)*264];
                a[2] = *(const uint32_t*)&smh[base + gid*264 + 8];
                a[3] = *(const uint32_t*)&smh[base + (gid+8)*264 + 8];
            } else {
                int jo = jb - 512 + tig*2;
                a[0] = hpack(smh[H_V + jo*18 + gid],       smh[H_V + (jo+1)*18 + gid]);
                a[1] = hpack(smh[H_V + jo*18 + gid + 8],   smh[H_V + (jo+1)*18 + gid + 8]);
                a[2] = hpack(smh[H_V + (jo+8)*18 + gid],   smh[H_V + (jo+9)*18 + gid]);
                a[3] = hpack(smh[H_V + (jo+8)*18 + gid+8], smh[H_V + (jo+9)*18 + gid + 8]);
            }
            b[0] = *(const uint32_t*)&smh[H_GW + gid*776 + jb + tig*2];
            b[1] = *(const uint32_t*)&smh[H_GW + gid*776 + jb + tig*2 + 8];
            mma_16816(c, a, b);
        }
        *(float2*)&sm[S_GP + warp*128 + gid*8 + tig*2]     = make_float2(c[0], c[1]);
        *(float2*)&sm[S_GP + warp*128 + (gid+8)*8 + tig*2] = make_float2(c[2], c[3]);
    }
    __syncthreads();

    // --- D2: reduce 8 warp partials -> ig/fg preacts ---
    if (tid < 128) {
        int t = tid >> 3, g = tid & 7;
        float s2 = 0.f;
#pragma unroll
        for (int w = 0; w < 8; w++) s2 += sm[S_GP + w*128 + tid];
        if (g < 4) sm[S_IG + t*4 + g]       = s2 + ig_b[g];
        else       sm[S_FG + t*4 + (g-4)]   = s2 + fg_b[g-4];
    }
    __syncthreads();

    // --- E: prefix scan of log-sigmoid(fg) (warps 0-1) ---
    if (tid < 64) {
        int h = tid >> 4, t = tid & 15;
        float fgv = sm[S_FG + t*4 + h];
        float cum = fminf(fgv, 0.f) - __logf(1.f + __expf(-fabsf(fgv)));
#pragma unroll
        for (int m = 1; m < 16; m <<= 1) {
            float o = __shfl_up_sync(0xffffffffu, cum, m, 16);
            if ((tid & 15) >= m) cum += o;
        }
        sm[S_LFC + h*17 + t + 1] = cum;
        if (t == 0) sm[S_LFC + h*17] = 0.f;
        sm[S_AA + h*16 + t] = sm[S_IG + t*4 + h] - cum;
    }

    // --- F1: qk via MMA. Per head Q[16x64] @ K^T -> qk fp32 in S_GP[h][s][t] ---
    {
        const int h = warp >> 1, nc = warp & 1;
        const int hd = h*64;
        float c[4] = {0.f, 0.f, 0.f, 0.f};
#pragma unroll
        for (int kc = 0; kc < 4; kc++) {
            int d0 = hd + kc*16 + tig*2;
            uint32_t a[4], b[2];
            a[0] = *(const uint32_t*)&smh[H_Q + gid*264 + d0];
            a[1] = *(const uint32_t*)&smh[H_Q + (gid+8)*264 + d0];
            a[2] = *(const uint32_t*)&smh[H_Q + gid*264 + d0 + 8];
            a[3] = *(const uint32_t*)&smh[H_Q + (gid+8)*264 + d0 + 8];
            b[0] = *(const uint32_t*)&smh[H_K + (nc*8+gid)*264 + d0];
            b[1] = *(const uint32_t*)&smh[H_K + (nc*8+gid)*264 + d0 + 8];
            mma_16816(c, a, b);
        }
        *(float2*)&sm[S_GP + h*256 + gid*16 + nc*8 + tig*2]     = make_float2(c[0], c[1]);
        *(float2*)&sm[S_GP + h*256 + (gid+8)*16 + nc*8 + tig*2] = make_float2(c[2], c[3]);
    }
    __syncthreads();

    // --- F2: D-weights + normalizer -> wm (fp16) ---
    const int mh = tid >> 6;
    const int ms = (tid >> 2) & 15;
    const int mtq = tid & 3;
    {
        float4 q4 = *(const float4*)&sm[S_GP + mh*256 + ms*16 + mtq*4];
        float qkv4[4] = {q4.x, q4.y, q4.z, q4.w};
        float cs = sm[S_LFC + mh*17 + ms + 1];
        float mloc = -1e30f;
        float ldv[4];
#pragma unroll
        for (int j = 0; j < 4; j++) {
            int t = mtq*4 + j;
            if (t <= ms) { ldv[j] = cs + sm[S_AA + mh*16 + t]; mloc = fmaxf(mloc, ldv[j]); }
            else ldv[j] = 0.f;
        }
        mloc = fmaxf(mloc, __shfl_xor_sync(0xffffffffu, mloc, 1));
        mloc = fmaxf(mloc, __shfl_xor_sync(0xffffffffu, mloc, 2));
        float cv[4]; float csum = 0.f;
#pragma unroll
        for (int j = 0; j < 4; j++) {
            int t = mtq*4 + j;
            cv[j] = (t <= ms) ? (qkv4[j]*0.125f) * __expf(ldv[j] - mloc) : 0.f;
            csum += cv[j];
        }
        csum += __shfl_xor_sync(0xffffffffu, csum, 1);
        csum += __shfl_xor_sync(0xffffffffu, csum, 2);
        float norm = fmaxf(fabsf(csum), __expf(-mloc)) + 1e-6f;
        float inv = 1.f / norm;
        int wb = H_WM + (mh*16 + ms)*16 + mtq*4;
        *(__half2*)&smh[wb]     = __float22half2_rn(make_float2(cv[0]*inv, cv[1]*inv));
        *(__half2*)&smh[wb + 2] = __float22half2_rn(make_float2(cv[2]*inv, cv[3]*inv));
    }
    __syncthreads();

    // --- G: out = wm @ v via MMA -> HT fp16 [s][264] (aliases dead XM) ---
    {
        const int h = warp >> 1;
        uint32_t a[4];
        int ab = H_WM + h*256 + gid*16 + tig*2;
        a[0] = *(const uint32_t*)&smh[ab];
        a[1] = *(const uint32_t*)&smh[ab + 128];
        a[2] = *(const uint32_t*)&smh[ab + 8];
        a[3] = *(const uint32_t*)&smh[ab + 136];
#pragma unroll
        for (int dc = 0; dc < 4; dc++) {
            int dbase = ((warp & 1)*4 + dc)*8;
            uint32_t b[2];
            int vb = H_V + (h*64 + dbase + gid)*18 + tig*2;
            b[0] = *(const uint32_t*)&smh[vb];
            b[1] = *(const uint32_t*)&smh[vb + 8];
            float c[4] = {0.f, 0.f, 0.f, 0.f};
            mma_16816(c, a, b);
            int i0 = h*64 + dbase + tig*2;
            *(__half2*)&smh[H_HT + gid*264 + i0] =
                __float22half2_rn(make_float2(c[0], c[1]));
            *(__half2*)&smh[H_HT + (gid+8)*264 + i0] =
                __float22half2_rn(make_float2(c[2], c[3]));
        }
    }
    __syncthreads();

    // --- H: group LayerNorm + skip*xc + silu(z), direct store to HS ---
    {
        int hD = tid >> 6, sD = (tid >> 2) & 15, dq = tid & 3;
        int ib0 = hD*64 + dq*16;
        uint4 r0 = *(const uint4*)&smh[H_HT + sD*264 + ib0];
        uint4 r1 = *(const uint4*)&smh[H_HT + sD*264 + ib0 + 8];
        float vals[16];
        unpack8(r0, vals);
        unpack8(r1, vals + 8);
        float sum = 0.f, sq = 0.f;
#pragma unroll
        for (int dd = 0; dd < 16; dd++) { sum += vals[dd]; sq += vals[dd]*vals[dd]; }
        sum += __shfl_xor_sync(0xffffffffu, sum, 1);
        sum += __shfl_xor_sync(0xffffffffu, sum, 2);
        sq  += __shfl_xor_sync(0xffffffffu, sq, 1);
        sq  += __shfl_xor_sync(0xffffffffu, sq, 2);
        float mu = sum * (1.f/64.f);
        float var = sq * (1.f/64.f) - mu*mu;
        float rstd = rsqrtf(var + 1e-5f);

        const __half* zrow = UP + (size_t)seq*8192 + sD*512 + 256 + ib0;
        __half* dst = HS + ((size_t)seq*16 + sD)*256 + ib0;
#pragma unroll
        for (int g2 = 0; g2 < 2; g2++) {
            float zz[8], xcv[8];
            unpack8(*(const uint4*)(zrow + g2*8), zz);
            unpack8(*(const uint4*)&smh[H_XC + sD*264 + ib0 + g2*8], xcv);
            float4 lw0 = *(const float4*)(ln_w + ib0 + g2*8);
            float4 lw1 = *(const float4*)(ln_w + ib0 + g2*8 + 4);
            float4 sk0 = *(const float4*)(skip + ib0 + g2*8);
            float4 sk1 = *(const float4*)(skip + ib0 + g2*8 + 4);
            float lw[8] = {lw0.x,lw0.y,lw0.z,lw0.w,lw1.x,lw1.y,lw1.z,lw1.w};
            float sk[8] = {sk0.x,sk0.y,sk0.z,sk0.w,sk1.x,sk1.y,sk1.z,sk1.w};
            __half2 op[4];
#pragma unroll
            for (int u = 0; u < 4; u++) {
                float o0 = ((vals[g2*8+2*u]   - mu)*rstd*lw[2*u]   + sk[2*u]  *xcv[2*u])   * siluf(zz[2*u]);
                float o1 = ((vals[g2*8+2*u+1] - mu)*rstd*lw[2*u+1] + sk[2*u+1]*xcv[2*u+1]) * siluf(zz[2*u+1]);
                op[u] = __float22half2_rn(make_float2(o0, o1));
            }
            *(uint4*)(dst + g2*8) = *(uint4*)op;
        }
    }
}

// ---------------- launch ----------------
extern "C" void kernel_launch(void* const* d_in, const int* in_sizes, int n_in,
                              void* d_out, int out_size) {
    const float* x      = (const float*)d_in[0];
    const float* W_up   = (const float*)d_in[1];
    const float* conv_w = (const float*)d_in[2];
    const float* conv_b = (const float*)d_in[3];
    const float* Wq     = (const float*)d_in[4];
    const float* Wk     = (const float*)d_in[5];
    const float* Wv     = (const float*)d_in[6];
    const float* ig_w   = (const float*)d_in[7];
    const float* ig_b   = (const float*)d_in[8];
    const float* fg_w   = (const float*)d_in[9];
    const float* fg_b   = (const float*)d_in[10];
    const float* ln_w   = (const float*)d_in[11];
    const float* skip   = (const float*)d_in[12];
    const float* W_down = (const float*)d_in[13];
    float* out = (float*)d_out;

    __half *XS, *UP, *HS, *WTU, *WTD, *GW;
    float *OT;
    cudaGetSymbolAddress((void**)&XS,  g_XS);
    cudaGetSymbolAddress((void**)&UP,  g_UP);
    cudaGetSymbolAddress((void**)&HS,  g_HS);
    cudaGetSymbolAddress((void**)&OT,  g_OT);
    cudaGetSymbolAddress((void**)&WTU, g_WTU);
    cudaGetSymbolAddress((void**)&WTD, g_WTD);
    cudaGetSymbolAddress((void**)&GW,  g_GW);

    cudaFuncSetAttribute(k_seq, cudaFuncAttributeMaxDynamicSharedMemorySize,
                         SM3_FLOATS * (int)sizeof(float));

    k_transpose_in<<<4096, 256>>>(x, XS);
    k_prep<<<408, 256>>>(W_up, W_down, ig_w, fg_w, WTU, WTD, GW);
    // up: UP[131072,512] = XS[131072,128] @ WTU[512,128]^T  (fp16 out)
    k_gemm_h<true><<<dim3(4, 1024), 256>>>(XS, WTU, UP, 512, 128);
    k_seq<<<SEQS, 256, SM3_FLOATS * sizeof(float)>>>(UP, conv_w, conv_b,
        Wq, Wk, Wv, GW, ig_b, fg_b, ln_w, skip, HS);
    // down: OT[131072,128] = HS[131072,256] @ WTD[128,256]^T (fp32 out)
    k_gemm_h<false><<<dim3(1, 1024), 256>>>(HS, WTD, OT, 128, 256);
    k_transpose_out<<<4096, 256>>>(OT, out);
}

// round 13
// speedup vs baseline: 2.3008x; 1.0581x over previous
#include <cuda_runtime.h>
#include <cuda_fp16.h>
#include <cstdint>
#include <math.h>

// ---------------- problem constants ----------------
#define DIMC  128
#define TT    16
#define INNER 256
#define SEQS  8192
#define ROWS  (SEQS*TT)         // 131072
#define UPCOLS 512

// ---------------- scratch (static device, no allocs) ----------------
__device__ __half g_XS[(size_t)ROWS*DIMC];   // [row][128] fp16
__device__ __half g_UP[(size_t)ROWS*UPCOLS]; // [row][512] fp16
__device__ __half g_HS[(size_t)ROWS*INNER];  // [row][256] fp16
__device__ float  g_OT[(size_t)ROWS*DIMC];   // [row][128] fp32
__device__ __half g_WTU[512*128];            // W_up^T  [n][k] fp16
__device__ __half g_WTD[128*256];            // W_down^T [n][k] fp16
__device__ __half g_GW[8*776];               // gate weights g-major [g][776]

// ---------------- helpers ----------------
__device__ __forceinline__ float siluf(float x){ return x / (1.f + __expf(-x)); }
__device__ __forceinline__ uint32_t smem_u32(const void* p){
    uint32_t a;
    asm("{ .reg .u64 t; cvta.to.shared.u64 t, %1; cvt.u32.u64 %0, t; }" : "=r"(a) : "l"(p));
    return a;
}
__device__ __forceinline__ uint32_t hpack(__half lo, __half hi){
    __half2 h = __halves2half2(lo, hi);
    return *(uint32_t*)&h;
}
__device__ __forceinline__ void mma_16816(float* c, const uint32_t* a, const uint32_t* b){
    asm volatile(
        "mma.sync.aligned.m16n8k16.row.col.f32.f16.f16.f32 "
        "{%0,%1,%2,%3}, {%4,%5,%6,%7}, {%8,%9}, {%0,%1,%2,%3};"
        : "+f"(c[0]), "+f"(c[1]), "+f"(c[2]), "+f"(c[3])
        : "r"(a[0]), "r"(a[1]), "r"(a[2]), "r"(a[3]), "r"(b[0]), "r"(b[1]));
}
__device__ __forceinline__ void unpack8(uint4 v, float* f){
    const __half2* hp = (const __half2*)&v;
#pragma unroll
    for (int u = 0; u < 4; u++) {
        float2 t = __half22float2(hp[u]);
        f[2*u] = t.x; f[2*u+1] = t.y;
    }
}
__device__ __forceinline__ void unpack4(uint2 v, float* f){
    const __half2* hp = (const __half2*)&v;
    float2 t0 = __half22float2(hp[0]);
    float2 t1 = __half22float2(hp[1]);
    f[0] = t0.x; f[1] = t0.y; f[2] = t1.x; f[3] = t1.y;
}

// ---------------- kernel: (b,c,t,h,w) -> XS[seq][t][c] (fp16) ----------------
__global__ void __launch_bounds__(256) k_transpose_in(const float* __restrict__ x,
                                                      __half* __restrict__ XS) {
    __shared__ float tile[128*33];
    int bid = blockIdx.x;
    int b = bid >> 9;
    int t = (bid >> 5) & 15;
    int h = bid & 31;
    const float* src = x + ((size_t)(b*128)*16 + t) * 1024 + h*32;
    for (int idx = threadIdx.x; idx < 128*32; idx += 256) {
        int c = idx >> 5, w = idx & 31;
        tile[c*33 + w] = src[(size_t)c*16384 + w];
    }
    __syncthreads();
    size_t base = ((size_t)(b*1024 + h*32) * 16 + t) * 128;
    for (int idx = threadIdx.x; idx < 2048; idx += 256) {
        int w = idx >> 6, c2 = idx & 63;
        __half2 v = __float22half2_rn(make_float2(tile[(2*c2)*33 + w],
                                                  tile[(2*c2+1)*33 + w]));
        *(__half2*)(XS + base + (size_t)w*2048 + 2*c2) = v;
    }
}

// ---------------- kernel: OT[row][c] -> out (b,c,t,h,w) ----------------
__global__ void __launch_bounds__(256) k_transpose_out(const float* __restrict__ OT,
                                                       float* __restrict__ out) {
    __shared__ float tile[128*33];
    int bid = blockIdx.x;
    int b = bid >> 9;
    int t = (bid >> 5) & 15;
    int h = bid & 31;
    size_t base = ((size_t)(b*1024 + h*32) * 16 + t) * 128;
    for (int idx = threadIdx.x; idx < 32*128; idx += 256) {
        int w = idx >> 7, c = idx & 127;
        tile[c*33 + w] = OT[base + (size_t)w*2048 + c];
    }
    __syncthreads();
    float* dst = out + ((size_t)(b*128)*16 + t) * 1024 + h*32;
    for (int idx = threadIdx.x; idx < 128*32; idx += 256) {
        int c = idx >> 5, w = idx & 31;
        dst[(size_t)c*16384 + w] = tile[c*33 + w];
    }
}

// ---------------- merged prep: WTU, WTD, GW (one launch) ----------------
__global__ void k_prep(const float* __restrict__ W_up, const float* __restrict__ W_down,
                       const float* __restrict__ ig_w, const float* __restrict__ fg_w,
                       __half* __restrict__ WTU, __half* __restrict__ WTD,
                       __half* __restrict__ GW){
    int blk = blockIdx.x;
    if (blk < 256) {
        int idx = blk*256 + threadIdx.x;
        int k = idx >> 9, n = idx & 511;
        WTU[(size_t)n*128 + k] = __float2half(W_up[idx]);
    } else if (blk < 384) {
        int idx = (blk-256)*256 + threadIdx.x;
        int k = idx >> 7, n = idx & 127;
        WTD[(size_t)n*256 + k] = __float2half(W_down[idx]);
    } else {
        int idx = (blk-384)*256 + threadIdx.x;
        if (idx < 6144) {
            int j = idx >> 3, g = idx & 7;
            float v = (g < 4) ? ig_w[j*4 + g] : fg_w[j*4 + (g-4)];
            GW[g*776 + j] = __float2half(v);
        }
    }
}

// ---------------- fp16 warp-MMA GEMM: C[M,Ng] = A[M,K] @ Bt[Ng,K]^T ----------------
template<bool HOUT>
__global__ void __launch_bounds__(256) k_gemm_h(const __half* __restrict__ A,
        const __half* __restrict__ Bt, void* __restrict__ Cv, int Ng, int Kf) {
    __shared__ __align__(16) __half As[2][128*40];
    __shared__ __align__(16) __half Bs[2][128*40];
    const int tid  = threadIdx.x;
    const int lane = tid & 31, warp = tid >> 5;
    const int gid  = lane >> 2, tig = lane & 3;
    const int wm0  = (warp >> 1) * 32;
    const int wn0  = (warp & 1) * 64;
    const int m0 = blockIdx.y * 128, n0 = blockIdx.x * 128;
    const int nk = Kf >> 5;

    uint32_t sA0 = smem_u32(As[0]), sA1 = smem_u32(As[1]);
    uint32_t sB0 = smem_u32(Bs[0]), sB1 = smem_u32(Bs[1]);

    float acc[2][8][4];
#pragma unroll
    for (int i = 0; i < 2; i++)
#pragma unroll
        for (int j = 0; j < 8; j++)
#pragma unroll
            for (int e = 0; e < 4; e++) acc[i][j][e] = 0.f;

    auto issue = [&](int kb, int buf){
        uint32_t da_base = buf ? sA1 : sA0;
        uint32_t db_base = buf ? sB1 : sB0;
#pragma unroll
        for (int r = 0; r < 2; r++) {
            int idx = tid + 256*r;
            int row = idx >> 2, c16 = idx & 3;
            const __half* ga = A  + (size_t)(m0+row)*Kf + kb + c16*8;
            const __half* gb = Bt + (size_t)(n0+row)*Kf + kb + c16*8;
            uint32_t da = da_base + row*80 + c16*16;
            uint32_t db = db_base + row*80 + c16*16;
            asm volatile("cp.async.cg.shared.global [%0], [%1], 16;" :: "r"(da), "l"(ga));
            asm volatile("cp.async.cg.shared.global [%0], [%1], 16;" :: "r"(db), "l"(gb));
        }
        asm volatile("cp.async.commit_group;");
    };

    issue(0, 0);
    for (int kc = 0; kc < nk; kc++) {
        if (kc + 1 < nk) {
            issue((kc+1)*32, (kc+1)&1);
            asm volatile("cp.async.wait_group 1;");
        } else {
            asm volatile("cp.async.wait_group 0;");
        }
        __syncthreads();
        const __half2* A2 = (const __half2*)As[kc&1];
        const __half2* B2 = (const __half2*)Bs[kc&1];
#pragma unroll
        for (int ks = 0; ks < 2; ks++) {
            const int k2b = ks*8;
            uint32_t a[2][4], b[8][2];
#pragma unroll
            for (int i = 0; i < 2; i++) {
                int r = wm0 + i*16 + gid;
                a[i][0] = *(const uint32_t*)&A2[r*20 + k2b + tig];
                a[i][1] = *(const uint32_t*)&A2[(r+8)*20 + k2b + tig];
                a[i][2] = *(const uint32_t*)&A2[r*20 + k2b + tig + 4];
                a[i][3] = *(const uint32_t*)&A2[(r+8)*20 + k2b + tig + 4];
            }
#pragma unroll
            for (int j = 0; j < 8; j++) {
                int rn = wn0 + j*8 + gid;
                b[j][0] = *(const uint32_t*)&B2[rn*20 + k2b + tig];
                b[j][1] = *(const uint32_t*)&B2[rn*20 + k2b + tig + 4];
            }
#pragma unroll
            for (int i = 0; i < 2; i++)
#pragma unroll
                for (int j = 0; j < 8; j++)
                    mma_16816(acc[i][j], a[i], b[j]);
        }
        __syncthreads();
    }
#pragma unroll
    for (int i = 0; i < 2; i++) {
        int row = m0 + wm0 + i*16 + gid;
#pragma unroll
        for (int j = 0; j < 8; j++) {
            int col = n0 + wn0 + j*8 + tig*2;
            if (HOUT) {
                __half* C = (__half*)Cv;
                *(__half2*)(C + (size_t)row*Ng + col) =
                    __float22half2_rn(make_float2(acc[i][j][0], acc[i][j][1]));
                *(__half2*)(C + (size_t)(row+8)*Ng + col) =
                    __float22half2_rn(make_float2(acc[i][j][2], acc[i][j][3]));
            } else {
                float* C = (float*)Cv;
                *(float2*)(C + (size_t)row*Ng + col)     = make_float2(acc[i][j][0], acc[i][j][1]);
                *(float2*)(C + (size_t)(row+8)*Ng + col) = make_float2(acc[i][j][2], acc[i][j][3]);
            }
        }
    }
}

// ---------------- per-sequence fused middle ----------------
// All big arrays fp16, row stride 264. HT aliases dead XM.
#define H_XM   0        // xm [t][264] fp16 (phases A/BC); HT [s][264] aliases after
#define H_HT   0
#define H_XC   4224     // xc [t][264]
#define H_Q    8448     // q  [t][264]
#define H_K    12672    // k  [t][264]
#define H_V    16896    // v  [t][264]  (t-major, like K)
#define H_GW   21120    // gate weights g-major [8][776] (6208 h)
#define H_WM   27328    // wm [h][s][t] (1024 h) ends 28352
// float arrays resume: 28352/2 = 14176
#define S_GP   14176    // 1024 f scratch: gate partials / qk fp32
#define S_IG   15200    // [t][4]
#define S_FG   15264    // [t][4]
#define S_LFC  15328    // [h][17]
#define S_AA   15396    // [h][16]
#define SM3_FLOATS 15460   // 61.8 KB

__global__ void __launch_bounds__(256,3) k_seq(
    const __half* __restrict__ UP,
    const float* __restrict__ conv_w, const float* __restrict__ conv_b,
    const float* __restrict__ Wq, const float* __restrict__ Wk, const float* __restrict__ Wv,
    const __half* __restrict__ GW,
    const float* __restrict__ ig_b, const float* __restrict__ fg_b,
    const float* __restrict__ ln_w, const float* __restrict__ skip,
    __half* __restrict__ HS) {
    extern __shared__ float sm[];
    __half* smh = (__half*)sm;
    const int tid = threadIdx.x;
    const int seq = blockIdx.x;
    const int warp = tid >> 5, lane = tid & 31;
    const int gid = lane >> 2, tig = lane & 3;

    // --- A: copy x_m (fp16, [t][264]) + gate weights into smem ---
    {
        const uint4* src = (const uint4*)(UP + (size_t)seq * 16 * 512);
#pragma unroll
        for (int rr = 0; rr < 2; rr++) {
            int i = tid + 256*rr;            // 0..511 (16 rows x 32 uint4)
            int row = i >> 5, q = i & 31;
            *(uint4*)&smh[H_XM + row*264 + q*8] = src[row*64 + q];
        }
        const uint4* gsrc = (const uint4*)GW;
        uint4* gdst = (uint4*)&smh[H_GW];
        for (int r = tid; r < 776; r += 256) gdst[r] = gsrc[r];
    }
    __syncthreads();

    // --- BC: fused conv+silu -> xc, then block-diagonal q,k,v ---
    {
        const int n = tid & 63;
        const int t0 = tid >> 6;
        float4 cw[4];
#pragma unroll
        for (int j = 0; j < 4; j++) cw[j] = *(const float4*)(conv_w + j*256 + n*4);
        const float4 cb = *(const float4*)(conv_b + n*4);
#pragma unroll
        for (int r = 0; r < 4; r++) {
            int t = t0 + r*4;
            float a0 = cb.x, a1 = cb.y, a2 = cb.z, a3 = cb.w;
            float xm_t[4];
#pragma unroll
            for (int j = 0; j < 4; j++) {
                int tt = t + j - 3;
                if (tt >= 0) {
                    float xm[4];
                    unpack4(*(const uint2*)&smh[H_XM + tt*264 + n*4], xm);
                    a0 += cw[j].x*xm[0]; a1 += cw[j].y*xm[1];
                    a2 += cw[j].z*xm[2]; a3 += cw[j].w*xm[3];
                    if (j == 3) { xm_t[0]=xm[0]; xm_t[1]=xm[1]; xm_t[2]=xm[2]; xm_t[3]=xm[3]; }
                }
            }
            float xc[4];
            xc[0] = siluf(a0); xc[1] = siluf(a1);
            xc[2] = siluf(a2); xc[3] = siluf(a3);
            *(__half2*)&smh[H_XC + t*264 + n*4]     = __float22half2_rn(make_float2(xc[0], xc[1]));
            *(__half2*)&smh[H_XC + t*264 + n*4 + 2] = __float22half2_rn(make_float2(xc[2], xc[3]));
            float qv[4], kv[4], vv[4];
#pragma unroll
            for (int o = 0; o < 4; o++) {
                float4 wq = *(const float4*)(Wq + n*16 + o*4);
                float4 wk = *(const float4*)(Wk + n*16 + o*4);
                float4 wv = *(const float4*)(Wv + n*16 + o*4);
                qv[o] = xc[0]*wq.x + xc[1]*wq.y + xc[2]*wq.z + xc[3]*wq.w;
                kv[o] = xc[0]*wk.x + xc[1]*wk.y + xc[2]*wk.z + xc[3]*wk.w;
                vv[o] = xm_t[0]*wv.x + xm_t[1]*wv.y + xm_t[2]*wv.z + xm_t[3]*wv.w;
            }
            *(__half2*)&smh[H_Q + t*264 + n*4]     = __float22half2_rn(make_float2(qv[0], qv[1]));
            *(__half2*)&smh[H_Q + t*264 + n*4 + 2] = __float22half2_rn(make_float2(qv[2], qv[3]));
            *(__half2*)&smh[H_K + t*264 + n*4]     = __float22half2_rn(make_float2(kv[0], kv[1]));
            *(__half2*)&smh[H_K + t*264 + n*4 + 2] = __float22half2_rn(make_float2(kv[2], kv[3]));
            *(__half2*)&smh[H_V + t*264 + n*4]     = __float22half2_rn(make_float2(vv[0], vv[1]));
            *(__half2*)&smh[H_V + t*264 + n*4 + 2] = __float22half2_rn(make_float2(vv[2], vv[3]));
        }
    }
    __syncthreads();

    // --- D: gates via MMA. if_in[16 x 768] @ GW^T[768 x 8]; warp w owns j in [w*96, (w+1)*96) ---
    {
        float c[4] = {0.f, 0.f, 0.f, 0.f};
#pragma unroll
        for (int ck = 0; ck < 6; ck++) {
            int jb = warp*96 + ck*16;
            int base;
            if (jb < 256)      base = H_Q + jb;
            else if (jb < 512) base = H_K + (jb - 256);
            else               base = H_V + (jb - 512);
            uint32_t a[4], b[2];
            a[0] = *(const uint32_t*)&smh[base + gid*264 + tig*2];
            a[1] = *(const uint32_t*)&smh[base + (gid+8)*264 + tig*2];
            a[2] = *(const uint32_t*)&smh[base + gid*264 + tig*2 + 8];
            a[3] = *(const uint32_t*)&smh[base + (gid+8)*264 + tig*2 + 8];
            b[0] = *(const uint32_t*)&smh[H_GW + gid*776 + jb + tig*2];
            b[1] = *(const uint32_t*)&smh[H_GW + gid*776 + jb + tig*2 + 8];
            mma_16816(c, a, b);
        }
        *(float2*)&sm[S_GP + warp*128 + gid*8 + tig*2]     = make_float2(c[0], c[1]);
        *(float2*)&sm[S_GP + warp*128 + (gid+8)*8 + tig*2] = make_float2(c[2], c[3]);
    }
    __syncthreads();

    // --- D2: reduce 8 warp partials -> ig/fg preacts ---
    if (tid < 128) {
        int t = tid >> 3, g = tid & 7;
        float s2 = 0.f;
#pragma unroll
        for (int w = 0; w < 8; w++) s2 += sm[S_GP + w*128 + tid];
        if (g < 4) sm[S_IG + t*4 + g]       = s2 + ig_b[g];
        else       sm[S_FG + t*4 + (g-4)]   = s2 + fg_b[g-4];
    }
    __syncthreads();

    // --- E: prefix scan of log-sigmoid(fg) (warps 0-1) ---
    if (tid < 64) {
        int h = tid >> 4, t = tid & 15;
        float fgv = sm[S_FG + t*4 + h];
        float cum = fminf(fgv, 0.f) - __logf(1.f + __expf(-fabsf(fgv)));
#pragma unroll
        for (int m = 1; m < 16; m <<= 1) {
            float o = __shfl_up_sync(0xffffffffu, cum, m, 16);
            if ((tid & 15) >= m) cum += o;
        }
        sm[S_LFC + h*17 + t + 1] = cum;
        if (t == 0) sm[S_LFC + h*17] = 0.f;
        sm[S_AA + h*16 + t] = sm[S_IG + t*4 + h] - cum;
    }

    // --- F1: qk via MMA. Per head Q[16x64] @ K^T -> qk fp32 in S_GP[h][s][t] ---
    {
        const int h = warp >> 1, nc = warp & 1;
        const int hd = h*64;
        float c[4] = {0.f, 0.f, 0.f, 0.f};
#pragma unroll
        for (int kc = 0; kc < 4; kc++) {
            int d0 = hd + kc*16 + tig*2;
            uint32_t a[4], b[2];
            a[0] = *(const uint32_t*)&smh[H_Q + gid*264 + d0];
            a[1] = *(const uint32_t*)&smh[H_Q + (gid+8)*264 + d0];
            a[2] = *(const uint32_t*)&smh[H_Q + gid*264 + d0 + 8];
            a[3] = *(const uint32_t*)&smh[H_Q + (gid+8)*264 + d0 + 8];
            b[0] = *(const uint32_t*)&smh[H_K + (nc*8+gid)*264 + d0];
            b[1] = *(const uint32_t*)&smh[H_K + (nc*8+gid)*264 + d0 + 8];
            mma_16816(c, a, b);
        }
        *(float2*)&sm[S_GP + h*256 + gid*16 + nc*8 + tig*2]     = make_float2(c[0], c[1]);
        *(float2*)&sm[S_GP + h*256 + (gid+8)*16 + nc*8 + tig*2] = make_float2(c[2], c[3]);
    }
    __syncthreads();

    // --- F2: D-weights + normalizer -> wm (fp16) ---
    const int mh = tid >> 6;
    const int ms = (tid >> 2) & 15;
    const int mtq = tid & 3;
    {
        float4 q4 = *(const float4*)&sm[S_GP + mh*256 + ms*16 + mtq*4];
        float qkv4[4] = {q4.x, q4.y, q4.z, q4.w};
        float cs = sm[S_LFC + mh*17 + ms + 1];
        float mloc = -1e30f;
        float ldv[4];
#pragma unroll
        for (int j = 0; j < 4; j++) {
            int t = mtq*4 + j;
            if (t <= ms) { ldv[j] = cs + sm[S_AA + mh*16 + t]; mloc = fmaxf(mloc, ldv[j]); }
            else ldv[j] = 0.f;
        }
        mloc = fmaxf(mloc, __shfl_xor_sync(0xffffffffu, mloc, 1));
        mloc = fmaxf(mloc, __shfl_xor_sync(0xffffffffu, mloc, 2));
        float cv[4]; float csum = 0.f;
#pragma unroll
        for (int j = 0; j < 4; j++) {
            int t = mtq*4 + j;
            cv[j] = (t <= ms) ? (qkv4[j]*0.125f) * __expf(ldv[j] - mloc) : 0.f;
            csum += cv[j];
        }
        csum += __shfl_xor_sync(0xffffffffu, csum, 1);
        csum += __shfl_xor_sync(0xffffffffu, csum, 2);
        float norm = fmaxf(fabsf(csum), __expf(-mloc)) + 1e-6f;
        float inv = 1.f / norm;
        int wb = H_WM + (mh*16 + ms)*16 + mtq*4;
        *(__half2*)&smh[wb]     = __float22half2_rn(make_float2(cv[0]*inv, cv[1]*inv));
        *(__half2*)&smh[wb + 2] = __float22half2_rn(make_float2(cv[2]*inv, cv[3]*inv));
    }
    __syncthreads();

    // --- G: out = wm @ v via MMA -> HT fp16 [s][264] (aliases dead XM) ---
    {
        const int h = warp >> 1;
        uint32_t a[4];
        int ab = H_WM + h*256 + gid*16 + tig*2;
        a[0] = *(const uint32_t*)&smh[ab];
        a[1] = *(const uint32_t*)&smh[ab + 128];
        a[2] = *(const uint32_t*)&smh[ab + 8];
        a[3] = *(const uint32_t*)&smh[ab + 136];
#pragma unroll
        for (int dc = 0; dc < 4; dc++) {
            int d = h*64 + ((warp & 1)*4 + dc)*8 + gid;
            uint32_t b[2];
            b[0] = hpack(smh[H_V + (tig*2)*264 + d],     smh[H_V + (tig*2+1)*264 + d]);
            b[1] = hpack(smh[H_V + (tig*2+8)*264 + d],   smh[H_V + (tig*2+9)*264 + d]);
            float c[4] = {0.f, 0.f, 0.f, 0.f};
            mma_16816(c, a, b);
            int i0 = h*64 + ((warp & 1)*4 + dc)*8 + tig*2;
            *(__half2*)&smh[H_HT + gid*264 + i0] =
                __float22half2_rn(make_float2(c[0], c[1]));
            *(__half2*)&smh[H_HT + (gid+8)*264 + i0] =
                __float22half2_rn(make_float2(c[2], c[3]));
        }
    }
    __syncthreads();

    // --- H: group LayerNorm + skip*xc + silu(z), direct store to HS ---
    {
        int hD = tid >> 6, sD = (tid >> 2) & 15, dq = tid & 3;
        int ib0 = hD*64 + dq*16;
        uint4 r0 = *(const uint4*)&smh[H_HT + sD*264 + ib0];
        uint4 r1 = *(const uint4*)&smh[H_HT + sD*264 + ib0 + 8];
        float vals[16];
        unpack8(r0, vals);
        unpack8(r1, vals + 8);
        float sum = 0.f, sq = 0.f;
#pragma unroll
        for (int dd = 0; dd < 16; dd++) { sum += vals[dd]; sq += vals[dd]*vals[dd]; }
        sum += __shfl_xor_sync(0xffffffffu, sum, 1);
        sum += __shfl_xor_sync(0xffffffffu, sum, 2);
        sq  += __shfl_xor_sync(0xffffffffu, sq, 1);
        sq  += __shfl_xor_sync(0xffffffffu, sq, 2);
        float mu = sum * (1.f/64.f);
        float var = sq * (1.f/64.f) - mu*mu;
        float rstd = rsqrtf(var + 1e-5f);

        const __half* zrow = UP + (size_t)seq*8192 + sD*512 + 256 + ib0;
        __half* dst = HS + ((size_t)seq*16 + sD)*256 + ib0;
#pragma unroll
        for (int g2 = 0; g2 < 2; g2++) {
            float zz[8], xcv[8];
            unpack8(*(const uint4*)(zrow + g2*8), zz);
            unpack8(*(const uint4*)&smh[H_XC + sD*264 + ib0 + g2*8], xcv);
            float4 lw0 = *(const float4*)(ln_w + ib0 + g2*8);
            float4 lw1 = *(const float4*)(ln_w + ib0 + g2*8 + 4);
            float4 sk0 = *(const float4*)(skip + ib0 + g2*8);
            float4 sk1 = *(const float4*)(skip + ib0 + g2*8 + 4);
            float lw[8] = {lw0.x,lw0.y,lw0.z,lw0.w,lw1.x,lw1.y,lw1.z,lw1.w};
            float sk[8] = {sk0.x,sk0.y,sk0.z,sk0.w,sk1.x,sk1.y,sk1.z,sk1.w};
            __half2 op[4];
#pragma unroll
            for (int u = 0; u < 4; u++) {
                float o0 = ((vals[g2*8+2*u]   - mu)*rstd*lw[2*u]   + sk[2*u]  *xcv[2*u])   * siluf(zz[2*u]);
                float o1 = ((vals[g2*8+2*u+1] - mu)*rstd*lw[2*u+1] + sk[2*u+1]*xcv[2*u+1]) * siluf(zz[2*u+1]);
                op[u] = __float22half2_rn(make_float2(o0, o1));
            }
            *(uint4*)(dst + g2*8) = *(uint4*)op;
        }
    }
}

// ---------------- launch ----------------
extern "C" void kernel_launch(void* const* d_in, const int* in_sizes, int n_in,
                              void* d_out, int out_size) {
    const float* x      = (const float*)d_in[0];
    const float* W_up   = (const float*)d_in[1];
    const float* conv_w = (const float*)d_in[2];
    const float* conv_b = (const float*)d_in[3];
    const float* Wq     = (const float*)d_in[4];
    const float* Wk     = (const float*)d_in[5];
    const float* Wv     = (const float*)d_in[6];
    const float* ig_w   = (const float*)d_in[7];
    const float* ig_b   = (const float*)d_in[8];
    const float* fg_w   = (const float*)d_in[9];
    const float* fg_b   = (const float*)d_in[10];
    const float* ln_w   = (const float*)d_in[11];
    const float* skip   = (const float*)d_in[12];
    const float* W_down = (const float*)d_in[13];
    float* out = (float*)d_out;

    __half *XS, *UP, *HS, *WTU, *WTD, *GW;
    float *OT;
    cudaGetSymbolAddress((void**)&XS,  g_XS);
    cudaGetSymbolAddress((void**)&UP,  g_UP);
    cudaGetSymbolAddress((void**)&HS,  g_HS);
    cudaGetSymbolAddress((void**)&OT,  g_OT);
    cudaGetSymbolAddress((void**)&WTU, g_WTU);
    cudaGetSymbolAddress((void**)&WTD, g_WTD);
    cudaGetSymbolAddress((void**)&GW,  g_GW);

    cudaFuncSetAttribute(k_seq, cudaFuncAttributeMaxDynamicSharedMemorySize,
                         SM3_FLOATS * (int)sizeof(float));

    k_transpose_in<<<4096, 256>>>(x, XS);
    k_prep<<<408, 256>>>(W_up, W_down, ig_w, fg_w, WTU, WTD, GW);
    // up: UP[131072,512] = XS[131072,128] @ WTU[512,128]^T  (fp16 out)
    k_gemm_h<true><<<dim3(4, 1024), 256>>>(XS, WTU, UP, 512, 128);
    k_seq<<<SEQS, 256, SM3_FLOATS * sizeof(float)>>>(UP, conv_w, conv_b,
        Wq, Wk, Wv, GW, ig_b, fg_b, ln_w, skip, HS);
    // down: OT[131072,128] = HS[131072,256] @ WTD[128,256]^T (fp32 out)
    k_gemm_h<false><<<dim3(1, 1024), 256>>>(HS, WTD, OT, 128, 256);
    k_transpose_out<<<4096, 256>>>(OT, out);
}

// round 14
// speedup vs baseline: 2.4195x; 1.0516x over previous
#include <cuda_runtime.h>
#include <cuda_fp16.h>
#include <cstdint>
#include <math.h>

// ---------------- problem constants ----------------
#define DIMC  128
#define TT    16
#define INNER 256
#define SEQS  8192
#define ROWS  (SEQS*TT)         // 131072
#define UPCOLS 512

// ---------------- scratch (static device, no allocs) ----------------
__device__ __half g_XS[(size_t)ROWS*DIMC];   // [row][128] fp16
__device__ __half g_UP[(size_t)ROWS*UPCOLS]; // [row][512] fp16
__device__ __half g_HS[(size_t)ROWS*INNER];  // [row][256] fp16
__device__ __half g_WTU[512*128];            // W_up^T  [n][k] fp16
__device__ __half g_WTD[128*256];            // W_down^T [n][k] fp16
__device__ __half g_GW[8*776];               // gate weights g-major [g][776]

// ---------------- helpers ----------------
__device__ __forceinline__ float siluf(float x){ return x / (1.f + __expf(-x)); }
__device__ __forceinline__ uint32_t smem_u32(const void* p){
    uint32_t a;
    asm("{ .reg .u64 t; cvta.to.shared.u64 t, %1; cvt.u32.u64 %0, t; }" : "=r"(a) : "l"(p));
    return a;
}
__device__ __forceinline__ uint32_t hpack(__half lo, __half hi){
    __half2 h = __halves2half2(lo, hi);
    return *(uint32_t*)&h;
}
__device__ __forceinline__ void mma_16816(float* c, const uint32_t* a, const uint32_t* b){
    asm volatile(
        "mma.sync.aligned.m16n8k16.row.col.f32.f16.f16.f32 "
        "{%0,%1,%2,%3}, {%4,%5,%6,%7}, {%8,%9}, {%0,%1,%2,%3};"
        : "+f"(c[0]), "+f"(c[1]), "+f"(c[2]), "+f"(c[3])
        : "r"(a[0]), "r"(a[1]), "r"(a[2]), "r"(a[3]), "r"(b[0]), "r"(b[1]));
}
__device__ __forceinline__ void unpack8(uint4 v, float* f){
    const __half2* hp = (const __half2*)&v;
#pragma unroll
    for (int u = 0; u < 4; u++) {
        float2 t = __half22float2(hp[u]);
        f[2*u] = t.x; f[2*u+1] = t.y;
    }
}
__device__ __forceinline__ void unpack4(uint2 v, float* f){
    const __half2* hp = (const __half2*)&v;
    float2 t0 = __half22float2(hp[0]);
    float2 t1 = __half22float2(hp[1]);
    f[0] = t0.x; f[1] = t0.y; f[2] = t1.x; f[3] = t1.y;
}

// ---------------- kernel: (b,c,t,h,w) -> XS[seq][t][c] (fp16) ----------------
__global__ void __launch_bounds__(256) k_transpose_in(const float* __restrict__ x,
                                                      __half* __restrict__ XS) {
    __shared__ float tile[128*33];
    int bid = blockIdx.x;
    int b = bid >> 9;
    int t = (bid >> 5) & 15;
    int h = bid & 31;
    const float* src = x + ((size_t)(b*128)*16 + t) * 1024 + h*32;
    for (int idx = threadIdx.x; idx < 128*32; idx += 256) {
        int c = idx >> 5, w = idx & 31;
        tile[c*33 + w] = src[(size_t)c*16384 + w];
    }
    __syncthreads();
    size_t base = ((size_t)(b*1024 + h*32) * 16 + t) * 128;
    for (int idx = threadIdx.x; idx < 2048; idx += 256) {
        int w = idx >> 6, c2 = idx & 63;
        __half2 v = __float22half2_rn(make_float2(tile[(2*c2)*33 + w],
                                                  tile[(2*c2+1)*33 + w]));
        *(__half2*)(XS + base + (size_t)w*2048 + 2*c2) = v;
    }
}

// ---------------- merged prep: WTU, WTD, GW (one launch) ----------------
__global__ void k_prep(const float* __restrict__ W_up, const float* __restrict__ W_down,
                       const float* __restrict__ ig_w, const float* __restrict__ fg_w,
                       __half* __restrict__ WTU, __half* __restrict__ WTD,
                       __half* __restrict__ GW){
    int blk = blockIdx.x;
    if (blk < 256) {
        int idx = blk*256 + threadIdx.x;
        int k = idx >> 9, n = idx & 511;
        WTU[(size_t)n*128 + k] = __float2half(W_up[idx]);
    } else if (blk < 384) {
        int idx = (blk-256)*256 + threadIdx.x;
        int k = idx >> 7, n = idx & 127;
        WTD[(size_t)n*256 + k] = __float2half(W_down[idx]);
    } else {
        int idx = (blk-384)*256 + threadIdx.x;
        if (idx < 6144) {
            int j = idx >> 3, g = idx & 7;
            float v = (g < 4) ? ig_w[j*4 + g] : fg_w[j*4 + (g-4)];
            GW[g*776 + j] = __float2half(v);
        }
    }
}

// ---------------- up-GEMM (fp16 out): UP = XS @ WTU^T ----------------
__global__ void __launch_bounds__(256) k_gemm_up(const __half* __restrict__ A,
        const __half* __restrict__ Bt, __half* __restrict__ C, int Ng, int Kf) {
    __shared__ __align__(16) __half As[2][128*40];
    __shared__ __align__(16) __half Bs[2][128*40];
    const int tid  = threadIdx.x;
    const int lane = tid & 31, warp = tid >> 5;
    const int gid  = lane >> 2, tig = lane & 3;
    const int wm0  = (warp >> 1) * 32;
    const int wn0  = (warp & 1) * 64;
    const int m0 = blockIdx.y * 128, n0 = blockIdx.x * 128;
    const int nk = Kf >> 5;

    uint32_t sA0 = smem_u32(As[0]), sA1 = smem_u32(As[1]);
    uint32_t sB0 = smem_u32(Bs[0]), sB1 = smem_u32(Bs[1]);

    float acc[2][8][4];
#pragma unroll
    for (int i = 0; i < 2; i++)
#pragma unroll
        for (int j = 0; j < 8; j++)
#pragma unroll
            for (int e = 0; e < 4; e++) acc[i][j][e] = 0.f;

    auto issue = [&](int kb, int buf){
        uint32_t da_base = buf ? sA1 : sA0;
        uint32_t db_base = buf ? sB1 : sB0;
#pragma unroll
        for (int r = 0; r < 2; r++) {
            int idx = tid + 256*r;
            int row = idx >> 2, c16 = idx & 3;
            const __half* ga = A  + (size_t)(m0+row)*Kf + kb + c16*8;
            const __half* gb = Bt + (size_t)(n0+row)*Kf + kb + c16*8;
            uint32_t da = da_base + row*80 + c16*16;
            uint32_t db = db_base + row*80 + c16*16;
            asm volatile("cp.async.cg.shared.global [%0], [%1], 16;" :: "r"(da), "l"(ga));
            asm volatile("cp.async.cg.shared.global [%0], [%1], 16;" :: "r"(db), "l"(gb));
        }
        asm volatile("cp.async.commit_group;");
    };

    issue(0, 0);
    for (int kc = 0; kc < nk; kc++) {
        if (kc + 1 < nk) {
            issue((kc+1)*32, (kc+1)&1);
            asm volatile("cp.async.wait_group 1;");
        } else {
            asm volatile("cp.async.wait_group 0;");
        }
        __syncthreads();
        const __half2* A2 = (const __half2*)As[kc&1];
        const __half2* B2 = (const __half2*)Bs[kc&1];
#pragma unroll
        for (int ks = 0; ks < 2; ks++) {
            const int k2b = ks*8;
            uint32_t a[2][4], b[8][2];
#pragma unroll
            for (int i = 0; i < 2; i++) {
                int r = wm0 + i*16 + gid;
                a[i][0] = *(const uint32_t*)&A2[r*20 + k2b + tig];
                a[i][1] = *(const uint32_t*)&A2[(r+8)*20 + k2b + tig];
                a[i][2] = *(const uint32_t*)&A2[r*20 + k2b + tig + 4];
                a[i][3] = *(const uint32_t*)&A2[(r+8)*20 + k2b + tig + 4];
            }
#pragma unroll
            for (int j = 0; j < 8; j++) {
                int rn = wn0 + j*8 + gid;
                b[j][0] = *(const uint32_t*)&B2[rn*20 + k2b + tig];
                b[j][1] = *(const uint32_t*)&B2[rn*20 + k2b + tig + 4];
            }
#pragma unroll
            for (int i = 0; i < 2; i++)
#pragma unroll
                for (int j = 0; j < 8; j++)
                    mma_16816(acc[i][j], a[i], b[j]);
        }
        __syncthreads();
    }
#pragma unroll
    for (int i = 0; i < 2; i++) {
        int row = m0 + wm0 + i*16 + gid;
#pragma unroll
        for (int j = 0; j < 8; j++) {
            int col = n0 + wn0 + j*8 + tig*2;
            *(__half2*)(C + (size_t)row*Ng + col) =
                __float22half2_rn(make_float2(acc[i][j][0], acc[i][j][1]));
            *(__half2*)(C + (size_t)(row+8)*Ng + col) =
                __float22half2_rn(make_float2(acc[i][j][2], acc[i][j][3]));
        }
    }
}

// ---------------- down-GEMM fused with output transpose ----------------
// OT[row][c] = HS[row][:256] @ WTD[c][:256]; row = seq*16+t, seq = b*1024+h*32+w.
// Each CTA: rows [y*128,(y+1)*128) = 8 consecutive seqs (same b,h; w=w0..w0+7).
// Epilogue: stage fp32 tile in smem [128][134], write out (b,c,t,h,w) directly.
#define DG_CS_STRIDE 134
#define DG_SMEM (128*DG_CS_STRIDE*4)   // 68608 B (aliases As/Bs region)

__global__ void __launch_bounds__(256) k_gemm_down(const __half* __restrict__ A,
        const __half* __restrict__ Bt, float* __restrict__ out) {
    extern __shared__ __align__(16) char dsm[];
    __half* As0 = (__half*)dsm;                    // [2][128*40]
    __half* Bs0 = (__half*)(dsm + 20480);          // [2][128*40]
    float*  Cs  = (float*)dsm;                     // [128][134] (aliases after mainloop)
    const int Kf = 256, Ng = 128;
    const int tid  = threadIdx.x;
    const int lane = tid & 31, warp = tid >> 5;
    const int gid  = lane >> 2, tig = lane & 3;
    const int wm0  = (warp >> 1) * 32;
    const int wn0  = (warp & 1) * 64;
    const int m0 = blockIdx.y * 128;

    uint32_t sA = smem_u32(As0);
    uint32_t sB = smem_u32(Bs0);

    float acc[2][8][4];
#pragma unroll
    for (int i = 0; i < 2; i++)
#pragma unroll
        for (int j = 0; j < 8; j++)
#pragma unroll
            for (int e = 0; e < 4; e++) acc[i][j][e] = 0.f;

    auto issue = [&](int kb, int buf){
        uint32_t da_base = sA + buf*10240;
        uint32_t db_base = sB + buf*10240;
#pragma unroll
        for (int r = 0; r < 2; r++) {
            int idx = tid + 256*r;
            int row = idx >> 2, c16 = idx & 3;
            const __half* ga = A  + (size_t)(m0+row)*Kf + kb + c16*8;
            const __half* gb = Bt + (size_t)row*Kf + kb + c16*8;
            uint32_t da = da_base + row*80 + c16*16;
            uint32_t db = db_base + row*80 + c16*16;
            asm volatile("cp.async.cg.shared.global [%0], [%1], 16;" :: "r"(da), "l"(ga));
            asm volatile("cp.async.cg.shared.global [%0], [%1], 16;" :: "r"(db), "l"(gb));
        }
        asm volatile("cp.async.commit_group;");
    };

    issue(0, 0);
    for (int kc = 0; kc < 8; kc++) {
        if (kc + 1 < 8) {
            issue((kc+1)*32, (kc+1)&1);
            asm volatile("cp.async.wait_group 1;");
        } else {
            asm volatile("cp.async.wait_group 0;");
        }
        __syncthreads();
        const __half2* A2 = (const __half2*)(As0 + (kc&1)*5120);
        const __half2* B2 = (const __half2*)(Bs0 + (kc&1)*5120);
#pragma unroll
        for (int ks = 0; ks < 2; ks++) {
            const int k2b = ks*8;
            uint32_t a[2][4], b[8][2];
#pragma unroll
            for (int i = 0; i < 2; i++) {
                int r = wm0 + i*16 + gid;
                a[i][0] = *(const uint32_t*)&A2[r*20 + k2b + tig];
                a[i][1] = *(const uint32_t*)&A2[(r+8)*20 + k2b + tig];
                a[i][2] = *(const uint32_t*)&A2[r*20 + k2b + tig + 4];
                a[i][3] = *(const uint32_t*)&A2[(r+8)*20 + k2b + tig + 4];
            }
#pragma unroll
            for (int j = 0; j < 8; j++) {
                int rn = wn0 + j*8 + gid;
                b[j][0] = *(const uint32_t*)&B2[rn*20 + k2b + tig];
                b[j][1] = *(const uint32_t*)&B2[rn*20 + k2b + tig + 4];
            }
#pragma unroll
            for (int i = 0; i < 2; i++)
#pragma unroll
                for (int j = 0; j < 8; j++)
                    mma_16816(acc[i][j], a[i], b[j]);
        }
        __syncthreads();
    }

    // stage acc -> Cs [row_local][col], stride 134 (float2-aligned, conflict-spread)
#pragma unroll
    for (int i = 0; i < 2; i++) {
        int r0 = wm0 + i*16 + gid;
#pragma unroll
        for (int j = 0; j < 8; j++) {
            int col = wn0 + j*8 + tig*2;
            *(float2*)&Cs[r0*DG_CS_STRIDE + col]     = make_float2(acc[i][j][0], acc[i][j][1]);
            *(float2*)&Cs[(r0+8)*DG_CS_STRIDE + col] = make_float2(acc[i][j][2], acc[i][j][3]);
        }
    }
    __syncthreads();

    // scatter: out[((b*128+c)*16+t)*1024 + h*32 + w0 + i] = Cs[(i*16+t)][c]
    {
        int seq0 = blockIdx.y * 8;
        int b = seq0 >> 10, rem = seq0 & 1023;
        int h = rem >> 5, w0 = rem & 31;
        float* obase = out + ((size_t)(b*128) * 16) * 1024 + h*32 + w0;
        for (int p = tid; p < 2048; p += 256) {
            int c = p >> 4, t = p & 15;
            float v[8];
#pragma unroll
            for (int i = 0; i < 8; i++) v[i] = Cs[(i*16 + t)*DG_CS_STRIDE + c];
            float* dst = obase + ((size_t)c*16 + t)*1024;
            *(float4*)dst     = make_float4(v[0], v[1], v[2], v[3]);
            *(float4*)(dst+4) = make_float4(v[4], v[5], v[6], v[7]);
        }
    }
}

// ---------------- per-sequence fused middle ----------------
// All big arrays fp16, row stride 264. HT aliases dead XM.
#define H_XM   0        // xm [t][264] fp16 (phases A/BC); HT [s][264] aliases after
#define H_HT   0
#define H_XC   4224     // xc [t][264]
#define H_Q    8448     // q  [t][264]
#define H_K    12672    // k  [t][264]
#define H_V    16896    // v  [t][264]  (t-major, like K)
#define H_GW   21120    // gate weights g-major [8][776] (6208 h)
#define H_WM   27328    // wm [h][s][t] (1024 h) ends 28352
// float arrays resume: 28352/2 = 14176
#define S_GP   14176    // 1024 f scratch: gate partials / qk fp32
#define S_IG   15200    // [t][4]
#define S_FG   15264    // [t][4]
#define S_LFC  15328    // [h][17]
#define S_AA   15396    // [h][16]
#define SM3_FLOATS 15460   // 61.8 KB

__global__ void __launch_bounds__(256,3) k_seq(
    const __half* __restrict__ UP,
    const float* __restrict__ conv_w, const float* __restrict__ conv_b,
    const float* __restrict__ Wq, const float* __restrict__ Wk, const float* __restrict__ Wv,
    const __half* __restrict__ GW,
    const float* __restrict__ ig_b, const float* __restrict__ fg_b,
    const float* __restrict__ ln_w, const float* __restrict__ skip,
    __half* __restrict__ HS) {
    extern __shared__ float sm[];
    __half* smh = (__half*)sm;
    const int tid = threadIdx.x;
    const int seq = blockIdx.x;
    const int warp = tid >> 5, lane = tid & 31;
    const int gid = lane >> 2, tig = lane & 3;

    // --- A: copy x_m (fp16, [t][264]) + gate weights into smem ---
    {
        const uint4* src = (const uint4*)(UP + (size_t)seq * 16 * 512);
#pragma unroll
        for (int rr = 0; rr < 2; rr++) {
            int i = tid + 256*rr;
            int row = i >> 5, q = i & 31;
            *(uint4*)&smh[H_XM + row*264 + q*8] = src[row*64 + q];
        }
        const uint4* gsrc = (const uint4*)GW;
        uint4* gdst = (uint4*)&smh[H_GW];
        for (int r = tid; r < 776; r += 256) gdst[r] = gsrc[r];
    }
    __syncthreads();

    // --- BC: fused conv+silu -> xc, then block-diagonal q,k,v ---
    {
        const int n = tid & 63;
        const int t0 = tid >> 6;
        float4 cw[4];
#pragma unroll
        for (int j = 0; j < 4; j++) cw[j] = *(const float4*)(conv_w + j*256 + n*4);
        const float4 cb = *(const float4*)(conv_b + n*4);
#pragma unroll
        for (int r = 0; r < 4; r++) {
            int t = t0 + r*4;
            float a0 = cb.x, a1 = cb.y, a2 = cb.z, a3 = cb.w;
            float xm_t[4];
#pragma unroll
            for (int j = 0; j < 4; j++) {
                int tt = t + j - 3;
                if (tt >= 0) {
                    float xm[4];
                    unpack4(*(const uint2*)&smh[H_XM + tt*264 + n*4], xm);
                    a0 += cw[j].x*xm[0]; a1 += cw[j].y*xm[1];
                    a2 += cw[j].z*xm[2]; a3 += cw[j].w*xm[3];
                    if (j == 3) { xm_t[0]=xm[0]; xm_t[1]=xm[1]; xm_t[2]=xm[2]; xm_t[3]=xm[3]; }
                }
            }
            float xc[4];
            xc[0] = siluf(a0); xc[1] = siluf(a1);
            xc[2] = siluf(a2); xc[3] = siluf(a3);
            *(__half2*)&smh[H_XC + t*264 + n*4]     = __float22half2_rn(make_float2(xc[0], xc[1]));
            *(__half2*)&smh[H_XC + t*264 + n*4 + 2] = __float22half2_rn(make_float2(xc[2], xc[3]));
            float qv[4], kv[4], vv[4];
#pragma unroll
            for (int o = 0; o < 4; o++) {
                float4 wq = *(const float4*)(Wq + n*16 + o*4);
                float4 wk = *(const float4*)(Wk + n*16 + o*4);
                float4 wv = *(const float4*)(Wv + n*16 + o*4);
                qv[o] = xc[0]*wq.x + xc[1]*wq.y + xc[2]*wq.z + xc[3]*wq.w;
                kv[o] = xc[0]*wk.x + xc[1]*wk.y + xc[2]*wk.z + xc[3]*wk.w;
                vv[o] = xm_t[0]*wv.x + xm_t[1]*wv.y + xm_t[2]*wv.z + xm_t[3]*wv.w;
            }
            *(__half2*)&smh[H_Q + t*264 + n*4]     = __float22half2_rn(make_float2(qv[0], qv[1]));
            *(__half2*)&smh[H_Q + t*264 + n*4 + 2] = __float22half2_rn(make_float2(qv[2], qv[3]));
            *(__half2*)&smh[H_K + t*264 + n*4]     = __float22half2_rn(make_float2(kv[0], kv[1]));
            *(__half2*)&smh[H_K + t*264 + n*4 + 2] = __float22half2_rn(make_float2(kv[2], kv[3]));
            *(__half2*)&smh[H_V + t*264 + n*4]     = __float22half2_rn(make_float2(vv[0], vv[1]));
            *(__half2*)&smh[H_V + t*264 + n*4 + 2] = __float22half2_rn(make_float2(vv[2], vv[3]));
        }
    }
    __syncthreads();

    // --- D: gates via MMA. if_in[16 x 768] @ GW^T[768 x 8]; warp w owns j in [w*96, (w+1)*96) ---
    {
        float c[4] = {0.f, 0.f, 0.f, 0.f};
#pragma unroll
        for (int ck = 0; ck < 6; ck++) {
            int jb = warp*96 + ck*16;
            int base;
            if (jb < 256)      base = H_Q + jb;
            else if (jb < 512) base = H_K + (jb - 256);
            else               base = H_V + (jb - 512);
            uint32_t a[4], b[2];
            a[0] = *(const uint32_t*)&smh[base + gid*264 + tig*2];
            a[1] = *(const uint32_t*)&smh[base + (gid+8)*264 + tig*2];
            a[2] = *(const uint32_t*)&smh[base + gid*264 + tig*2 + 8];
            a[3] = *(const uint32_t*)&smh[base + (gid+8)*264 + tig*2 + 8];
            b[0] = *(const uint32_t*)&smh[H_GW + gid*776 + jb + tig*2];
            b[1] = *(const uint32_t*)&smh[H_GW + gid*776 + jb + tig*2 + 8];
            mma_16816(c, a, b);
        }
        *(float2*)&sm[S_GP + warp*128 + gid*8 + tig*2]     = make_float2(c[0], c[1]);
        *(float2*)&sm[S_GP + warp*128 + (gid+8)*8 + tig*2] = make_float2(c[2], c[3]);
    }
    __syncthreads();

    // --- D2: reduce 8 warp partials -> ig/fg preacts ---
    if (tid < 128) {
        int t = tid >> 3, g = tid & 7;
        float s2 = 0.f;
#pragma unroll
        for (int w = 0; w < 8; w++) s2 += sm[S_GP + w*128 + tid];
        if (g < 4) sm[S_IG + t*4 + g]       = s2 + ig_b[g];
        else       sm[S_FG + t*4 + (g-4)]   = s2 + fg_b[g-4];
    }
    __syncthreads();

    // --- E: prefix scan of log-sigmoid(fg) (warps 0-1) ---
    if (tid < 64) {
        int h = tid >> 4, t = tid & 15;
        float fgv = sm[S_FG + t*4 + h];
        float cum = fminf(fgv, 0.f) - __logf(1.f + __expf(-fabsf(fgv)));
#pragma unroll
        for (int m = 1; m < 16; m <<= 1) {
            float o = __shfl_up_sync(0xffffffffu, cum, m, 16);
            if ((tid & 15) >= m) cum += o;
        }
        sm[S_LFC + h*17 + t + 1] = cum;
        if (t == 0) sm[S_LFC + h*17] = 0.f;
        sm[S_AA + h*16 + t] = sm[S_IG + t*4 + h] - cum;
    }

    // --- F1: qk via MMA. Per head Q[16x64] @ K^T -> qk fp32 in S_GP[h][s][t] ---
    {
        const int h = warp >> 1, nc = warp & 1;
        const int hd = h*64;
        float c[4] = {0.f, 0.f, 0.f, 0.f};
#pragma unroll
        for (int kc = 0; kc < 4; kc++) {
            int d0 = hd + kc*16 + tig*2;
            uint32_t a[4], b[2];
            a[0] = *(const uint32_t*)&smh[H_Q + gid*264 + d0];
            a[1] = *(const uint32_t*)&smh[H_Q + (gid+8)*264 + d0];
            a[2] = *(const uint32_t*)&smh[H_Q + gid*264 + d0 + 8];
            a[3] = *(const uint32_t*)&smh[H_Q + (gid+8)*264 + d0 + 8];
            b[0] = *(const uint32_t*)&smh[H_K + (nc*8+gid)*264 + d0];
            b[1] = *(const uint32_t*)&smh[H_K + (nc*8+gid)*264 + d0 + 8];
            mma_16816(c, a, b);
        }
        *(float2*)&sm[S_GP + h*256 + gid*16 + nc*8 + tig*2]     = make_float2(c[0], c[1]);
        *(float2*)&sm[S_GP + h*256 + (gid+8)*16 + nc*8 + tig*2] = make_float2(c[2], c[3]);
    }
    __syncthreads();

    // --- F2: D-weights + normalizer -> wm (fp16) ---
    const int mh = tid >> 6;
    const int ms = (tid >> 2) & 15;
    const int mtq = tid & 3;
    {
        float4 q4 = *(const float4*)&sm[S_GP + mh*256 + ms*16 + mtq*4];
        float qkv4[4] = {q4.x, q4.y, q4.z, q4.w};
        float cs = sm[S_LFC + mh*17 + ms + 1];
        float mloc = -1e30f;
        float ldv[4];
#pragma unroll
        for (int j = 0; j < 4; j++) {
            int t = mtq*4 + j;
            if (t <= ms) { ldv[j] = cs + sm[S_AA + mh*16 + t]; mloc = fmaxf(mloc, ldv[j]); }
            else ldv[j] = 0.f;
        }
        mloc = fmaxf(mloc, __shfl_xor_sync(0xffffffffu, mloc, 1));
        mloc = fmaxf(mloc, __shfl_xor_sync(0xffffffffu, mloc, 2));
        float cv[4]; float csum = 0.f;
#pragma unroll
        for (int j = 0; j < 4; j++) {
            int t = mtq*4 + j;
            cv[j] = (t <= ms) ? (qkv4[j]*0.125f) * __expf(ldv[j] - mloc) : 0.f;
            csum += cv[j];
        }
        csum += __shfl_xor_sync(0xffffffffu, csum, 1);
        csum += __shfl_xor_sync(0xffffffffu, csum, 2);
        float norm = fmaxf(fabsf(csum), __expf(-mloc)) + 1e-6f;
        float inv = 1.f / norm;
        int wb = H_WM + (mh*16 + ms)*16 + mtq*4;
        *(__half2*)&smh[wb]     = __float22half2_rn(make_float2(cv[0]*inv, cv[1]*inv));
        *(__half2*)&smh[wb + 2] = __float22half2_rn(make_float2(cv[2]*inv, cv[3]*inv));
    }
    __syncthreads();

    // --- G: out = wm @ v via MMA -> HT fp16 [s][264] (aliases dead XM) ---
    {
        const int h = warp >> 1;
        uint32_t a[4];
        int ab = H_WM + h*256 + gid*16 + tig*2;
        a[0] = *(const uint32_t*)&smh[ab];
        a[1] = *(const uint32_t*)&smh[ab + 128];
        a[2] = *(const uint32_t*)&smh[ab + 8];
        a[3] = *(const uint32_t*)&smh[ab + 136];
#pragma unroll
        for (int dc = 0; dc < 4; dc++) {
            int d = h*64 + ((warp & 1)*4 + dc)*8 + gid;
            uint32_t b[2];
            b[0] = hpack(smh[H_V + (tig*2)*264 + d],     smh[H_V + (tig*2+1)*264 + d]);
            b[1] = hpack(smh[H_V + (tig*2+8)*264 + d],   smh[H_V + (tig*2+9)*264 + d]);
            float c[4] = {0.f, 0.f, 0.f, 0.f};
            mma_16816(c, a, b);
            int i0 = h*64 + ((warp & 1)*4 + dc)*8 + tig*2;
            *(__half2*)&smh[H_HT + gid*264 + i0] =
                __float22half2_rn(make_float2(c[0], c[1]));
            *(__half2*)&smh[H_HT + (gid+8)*264 + i0] =
                __float22half2_rn(make_float2(c[2], c[3]));
        }
    }
    __syncthreads();

    // --- H: group LayerNorm + skip*xc + silu(z), direct store to HS ---
    {
        int hD = tid >> 6, sD = (tid >> 2) & 15, dq = tid & 3;
        int ib0 = hD*64 + dq*16;
        uint4 r0 = *(const uint4*)&smh[H_HT + sD*264 + ib0];
        uint4 r1 = *(const uint4*)&smh[H_HT + sD*264 + ib0 + 8];
        float vals[16];
        unpack8(r0, vals);
        unpack8(r1, vals + 8);
        float sum = 0.f, sq = 0.f;
#pragma unroll
        for (int dd = 0; dd < 16; dd++) { sum += vals[dd]; sq += vals[dd]*vals[dd]; }
        sum += __shfl_xor_sync(0xffffffffu, sum, 1);
        sum += __shfl_xor_sync(0xffffffffu, sum, 2);
        sq  += __shfl_xor_sync(0xffffffffu, sq, 1);
        sq  += __shfl_xor_sync(0xffffffffu, sq, 2);
        float mu = sum * (1.f/64.f);
        float var = sq * (1.f/64.f) - mu*mu;
        float rstd = rsqrtf(var + 1e-5f);

        const __half* zrow = UP + (size_t)seq*8192 + sD*512 + 256 + ib0;
        __half* dst = HS + ((size_t)seq*16 + sD)*256 + ib0;
#pragma unroll
        for (int g2 = 0; g2 < 2; g2++) {
            float zz[8], xcv[8];
            unpack8(*(const uint4*)(zrow + g2*8), zz);
            unpack8(*(const uint4*)&smh[H_XC + sD*264 + ib0 + g2*8], xcv);
            float4 lw0 = *(const float4*)(ln_w + ib0 + g2*8);
            float4 lw1 = *(const float4*)(ln_w + ib0 + g2*8 + 4);
            float4 sk0 = *(const float4*)(skip + ib0 + g2*8);
            float4 sk1 = *(const float4*)(skip + ib0 + g2*8 + 4);
            float lw[8] = {lw0.x,lw0.y,lw0.z,lw0.w,lw1.x,lw1.y,lw1.z,lw1.w};
            float sk[8] = {sk0.x,sk0.y,sk0.z,sk0.w,sk1.x,sk1.y,sk1.z,sk1.w};
            __half2 op[4];
#pragma unroll
            for (int u = 0; u < 4; u++) {
                float o0 = ((vals[g2*8+2*u]   - mu)*rstd*lw[2*u]   + sk[2*u]  *xcv[2*u])   * siluf(zz[2*u]);
                float o1 = ((vals[g2*8+2*u+1] - mu)*rstd*lw[2*u+1] + sk[2*u+1]*xcv[2*u+1]) * siluf(zz[2*u+1]);
                op[u] = __float22half2_rn(make_float2(o0, o1));
            }
            *(uint4*)(dst + g2*8) = *(uint4*)op;
        }
    }
}

// ---------------- launch ----------------
extern "C" void kernel_launch(void* const* d_in, const int* in_sizes, int n_in,
                              void* d_out, int out_size) {
    const float* x      = (const float*)d_in[0];
    const float* W_up   = (const float*)d_in[1];
    const float* conv_w = (const float*)d_in[2];
    const float* conv_b = (const float*)d_in[3];
    const float* Wq     = (const float*)d_in[4];
    const float* Wk     = (const float*)d_in[5];
    const float* Wv     = (const float*)d_in[6];
    const float* ig_w   = (const float*)d_in[7];
    const float* ig_b   = (const float*)d_in[8];
    const float* fg_w   = (const float*)d_in[9];
    const float* fg_b   = (const float*)d_in[10];
    const float* ln_w   = (const float*)d_in[11];
    const float* skip   = (const float*)d_in[12];
    const float* W_down = (const float*)d_in[13];
    float* out = (float*)d_out;

    __half *XS, *UP, *HS, *WTU, *WTD, *GW;
    cudaGetSymbolAddress((void**)&XS,  g_XS);
    cudaGetSymbolAddress((void**)&UP,  g_UP);
    cudaGetSymbolAddress((void**)&HS,  g_HS);
    cudaGetSymbolAddress((void**)&WTU, g_WTU);
    cudaGetSymbolAddress((void**)&WTD, g_WTD);
    cudaGetSymbolAddress((void**)&GW,  g_GW);

    cudaFuncSetAttribute(k_seq, cudaFuncAttributeMaxDynamicSharedMemorySize,
                         SM3_FLOATS * (int)sizeof(float));
    cudaFuncSetAttribute(k_gemm_down, cudaFuncAttributeMaxDynamicSharedMemorySize,
                         DG_SMEM);

    k_transpose_in<<<4096, 256>>>(x, XS);
    k_prep<<<408, 256>>>(W_up, W_down, ig_w, fg_w, WTU, WTD, GW);
    // up: UP[131072,512] = XS[131072,128] @ WTU[512,128]^T  (fp16 out)
    k_gemm_up<<<dim3(4, 1024), 256>>>(XS, WTU, UP, 512, 128);
    k_seq<<<SEQS, 256, SM3_FLOATS * sizeof(float)>>>(UP, conv_w, conv_b,
        Wq, Wk, Wv, GW, ig_b, fg_b, ln_w, skip, HS);
    // down + fused output transpose
    k_gemm_down<<<dim3(1, 1024), 256, DG_SMEM>>>(HS, WTD, out);
}